// round 14
// baseline (speedup 1.0000x reference)
#include <cuda_runtime.h>
#include <cuda_bf16.h>
#include <math.h>
#include <stdint.h>

// ---------------- problem constants ----------------
#define BB   64
#define SS   64
#define TT   32
#define EE   512
#define UU   1024
#define G4   (4*UU)      // 4096
#define U2   (2*UU)      // 2048
#define VD_  32000
#define RS   4           // recurrence K-split
#define RKC  (UU/RS)     // 256

// ---------------- device scratch (allocation-free contract) ----------------
__device__ __nv_bfloat16 g_XembEHi[BB*SS*EE];
__device__ __nv_bfloat16 g_XembELo[BB*SS*EE];
__device__ __nv_bfloat16 g_XembDHi[BB*TT*EE];
__device__ __nv_bfloat16 g_XembDLo[BB*TT*EE];
__device__ __nv_bfloat16 g_WeHi[G4*EE];
__device__ __nv_bfloat16 g_WeLo[G4*EE];
__device__ __nv_bfloat16 g_WidHi[G4*EE];
__device__ __nv_bfloat16 g_WidLo[G4*EE];
__device__ __nv_bfloat16 g_WdHi[(size_t)VD_*U2];
__device__ __nv_bfloat16 g_WdLo[(size_t)VD_*U2];
__device__ __nv_bfloat16 g_hcHi[(size_t)BB*TT*U2];   // [b*T+t][ctx|h] bf16 hi
__device__ __nv_bfloat16 g_hcLo[(size_t)BB*TT*U2];   // lo

// recurrence bf16 weights, reordered: tile bn covers all 4 gates for 32 u's
// enc (32 bn tiles): row' = bn*128 + g*32 + uu, orig = g*UU + bn*32 + uu
// dec (40 bn tiles): bn<8 -> Wa rows bn*128+rr ; bn>=8 -> g*UU + (bn-8)*32 + uu
__device__ __nv_bfloat16 g_WreHi[(size_t)G4*UU];
__device__ __nv_bfloat16 g_WreLo[(size_t)G4*UU];
__device__ __nv_bfloat16 g_WrdHi[(size_t)(UU+G4)*UU];
__device__ __nv_bfloat16 g_WrdLo[(size_t)(UU+G4)*UU];
// h double-buffered by step parity: read [par], write [par^1]
__device__ __nv_bfloat16 g_hHi[2][BB*UU];
__device__ __nv_bfloat16 g_hLo[2][BB*UU];

__device__ float g_Xe[(size_t)BB*SS*G4];            // x@W_ih_e^T + biases
__device__ float g_Xd[(size_t)BB*TT*G4];
__device__ float g_o [(size_t)BB*SS*UU];            // encoder outputs
__device__ float g_c [BB*UU];
__device__ float g_q [2][BB*UU];                    // q = h@Wa^T, parity-buffered
__device__ float g_p [(size_t)40*RS*64*128];        // per-bn K-split partials (5 MB)
__device__ int   g_ctr[64];                         // per-bn arrival counters

// ---------------- helpers ----------------
__device__ __forceinline__ float sigf(float x) { return 1.f / (1.f + expf(-x)); }

__device__ __forceinline__ void cp16(void* dst, const void* src) {
    uint32_t a;
    asm("{ .reg .u64 t; cvta.to.shared.u64 t, %1; cvt.u32.u64 %0, t; }"
        : "=r"(a) : "l"(dst));
    asm volatile("cp.async.cg.shared.global [%0], [%1], 16;" :: "r"(a), "l"(src));
}

__device__ __forceinline__ void mma16816(float* c, const uint32_t* a, const uint32_t* b) {
    asm volatile(
        "mma.sync.aligned.m16n8k16.row.col.f32.bf16.bf16.f32 "
        "{%0,%1,%2,%3}, {%4,%5,%6,%7}, {%8,%9}, {%0,%1,%2,%3};"
        : "+f"(c[0]), "+f"(c[1]), "+f"(c[2]), "+f"(c[3])
        : "r"(a[0]), "r"(a[1]), "r"(a[2]), "r"(a[3]), "r"(b[0]), "r"(b[1]));
}

__device__ __forceinline__ void split1(float x, __nv_bfloat16& h, __nv_bfloat16& l) {
    h = __float2bfloat16(x);
    l = __float2bfloat16(x - __bfloat162float(h));
}

// ---------------- fp32 -> bf16 hi/lo split ----------------
__global__ void k_split4(const float4* __restrict__ src,
                         __nv_bfloat162* __restrict__ hi,
                         __nv_bfloat162* __restrict__ lo, int n4)
{
    int base = blockIdx.x * blockDim.x + threadIdx.x;
    int stride = gridDim.x * blockDim.x;
#pragma unroll
    for (int it = 0; it < 4; it++) {
        int gid = base + it * stride;
        if (gid < n4) {
            float4 v = src[gid];
            __nv_bfloat16 hx, hy, hz, hw, lx, ly, lz, lw;
            split1(v.x, hx, lx); split1(v.y, hy, ly);
            split1(v.z, hz, lz); split1(v.w, hw, lw);
            __nv_bfloat162 a; a.x = hx; a.y = hy;
            __nv_bfloat162 b; b.x = hz; b.y = hw;
            __nv_bfloat162 c; c.x = lx; c.y = ly;
            __nv_bfloat162 d; d.x = lz; d.y = lw;
            hi[gid * 2] = a; hi[gid * 2 + 1] = b;
            lo[gid * 2] = c; lo[gid * 2 + 1] = d;
        }
    }
}

// ---------------- reorder + split for recurrence weights ----------------
__global__ void k_split_reord_enc(const float4* __restrict__ W) {
    int gid = blockIdx.x * blockDim.x + threadIdx.x;   // G4 * 256
    int rp = gid >> 8, c = gid & 255;
    int bn = rp >> 7, rr = rp & 127;
    int g = rr >> 5, uu = rr & 31;
    int orig = g * UU + bn * 32 + uu;
    float4 v = W[(size_t)orig * 256 + c];
    __nv_bfloat16 hx, hy, hz, hw, lx, ly, lz, lw;
    split1(v.x, hx, lx); split1(v.y, hy, ly);
    split1(v.z, hz, lz); split1(v.w, hw, lw);
    __nv_bfloat162 a; a.x = hx; a.y = hy;
    __nv_bfloat162 b; b.x = hz; b.y = hw;
    __nv_bfloat162 cc; cc.x = lx; cc.y = ly;
    __nv_bfloat162 dd; dd.x = lz; dd.y = lw;
    ((__nv_bfloat162*)g_WreHi)[gid * 2] = a; ((__nv_bfloat162*)g_WreHi)[gid * 2 + 1] = b;
    ((__nv_bfloat162*)g_WreLo)[gid * 2] = cc; ((__nv_bfloat162*)g_WreLo)[gid * 2 + 1] = dd;
}

__global__ void k_split_reord_dec(const float4* __restrict__ Wa,
                                  const float4* __restrict__ Whh) {
    int gid = blockIdx.x * blockDim.x + threadIdx.x;   // (UU+G4) * 256
    int rp = gid >> 8, c = gid & 255;
    int bn = rp >> 7, rr = rp & 127;
    const float4* src;
    int orig;
    if (bn < 8) { src = Wa;  orig = bn * 128 + rr; }
    else {
        int g = rr >> 5, uu = rr & 31;
        src = Whh; orig = g * UU + (bn - 8) * 32 + uu;
    }
    float4 v = src[(size_t)orig * 256 + c];
    __nv_bfloat16 hx, hy, hz, hw, lx, ly, lz, lw;
    split1(v.x, hx, lx); split1(v.y, hy, ly);
    split1(v.z, hz, lz); split1(v.w, hw, lw);
    __nv_bfloat162 a; a.x = hx; a.y = hy;
    __nv_bfloat162 b; b.x = hz; b.y = hw;
    __nv_bfloat162 cc; cc.x = lx; cc.y = ly;
    __nv_bfloat162 dd; dd.x = lz; dd.y = lw;
    ((__nv_bfloat162*)g_WrdHi)[gid * 2] = a; ((__nv_bfloat162*)g_WrdHi)[gid * 2 + 1] = b;
    ((__nv_bfloat162*)g_WrdLo)[gid * 2] = cc; ((__nv_bfloat162*)g_WrdLo)[gid * 2 + 1] = dd;
}

// ---------------- embedding gathers (write bf16 hi/lo) ----------------
__global__ void k_gather_enc(const int* __restrict__ x, const float* __restrict__ emb) {
    int gid = blockIdx.x * blockDim.x + threadIdx.x;      // BB*SS*(EE/4)
    const int E4 = EE / 4;
    int r = gid / E4, c = gid % E4;
    float4 v = ((const float4*)emb)[(size_t)x[r] * E4 + c];
    __nv_bfloat16 hx, hy, hz, hw, lx, ly, lz, lw;
    split1(v.x, hx, lx); split1(v.y, hy, ly);
    split1(v.z, hz, lz); split1(v.w, hw, lw);
    size_t pi = (size_t)r * (EE / 2) + c * 2;
    __nv_bfloat162 a; a.x = hx; a.y = hy; ((__nv_bfloat162*)g_XembEHi)[pi] = a;
    __nv_bfloat162 b; b.x = hz; b.y = hw; ((__nv_bfloat162*)g_XembEHi)[pi + 1] = b;
    __nv_bfloat162 cc; cc.x = lx; cc.y = ly; ((__nv_bfloat162*)g_XembELo)[pi] = cc;
    __nv_bfloat162 dd; dd.x = lz; dd.y = lw; ((__nv_bfloat162*)g_XembELo)[pi + 1] = dd;
}

__global__ void k_gather_dec(const int* __restrict__ y, const float* __restrict__ emb) {
    int gid = blockIdx.x * blockDim.x + threadIdx.x;      // BB*TT*(EE/4)
    const int E4 = EE / 4;
    int r = gid / E4, c = gid % E4;
    int b = r / TT, t = r % TT;
    int id = y[b * (TT + 1) + t];
    float4 v = ((const float4*)emb)[(size_t)id * E4 + c];
    __nv_bfloat16 hx, hy, hz, hw, lx, ly, lz, lw;
    split1(v.x, hx, lx); split1(v.y, hy, ly);
    split1(v.z, hz, lz); split1(v.w, hw, lw);
    size_t pi = (size_t)r * (EE / 2) + c * 2;
    __nv_bfloat162 a; a.x = hx; a.y = hy; ((__nv_bfloat162*)g_XembDHi)[pi] = a;
    __nv_bfloat162 b2; b2.x = hz; b2.y = hw; ((__nv_bfloat162*)g_XembDHi)[pi + 1] = b2;
    __nv_bfloat162 cc; cc.x = lx; cc.y = ly; ((__nv_bfloat162*)g_XembDLo)[pi] = cc;
    __nv_bfloat162 dd; dd.x = lz; dd.y = lw; ((__nv_bfloat162*)g_XembDLo)[pi + 1] = dd;
}

__global__ void k_init_state() {
    int gid = blockIdx.x * blockDim.x + threadIdx.x;
    if (gid < BB * UU) {
        g_c[gid] = 0.f;
        g_hHi[0][gid] = __float2bfloat16(0.f);
        g_hLo[0][gid] = __float2bfloat16(0.f);
        g_hHi[1][gid] = __float2bfloat16(0.f);
        g_hLo[1][gid] = __float2bfloat16(0.f);
    }
    if (gid < 64) g_ctr[gid] = 0;
}

// ---------------- HMMA bf16x2-compensated GEMM (big, 128x128 tile) ----------------
#define PITCH   80
#define ARR_SZ  (128 * PITCH)           // 10240
#define STG_SZ  (4 * ARR_SZ)            // 40960
#define OFF_AHI 0
#define OFF_ALO ARR_SZ
#define OFF_BHI (2 * ARR_SZ)
#define OFF_BLO (3 * ARR_SZ)
#define SMEM_DYN (2 * STG_SZ)           // 80 KB

template <int MODE>
__global__ void __launch_bounds__(256)
k_hmma(const __nv_bfloat16* __restrict__ Ahi, const __nv_bfloat16* __restrict__ Alo,
       const __nv_bfloat16* __restrict__ Bhi, const __nv_bfloat16* __restrict__ Blo,
       const float* __restrict__ bias1, const float* __restrict__ bias2,
       float* __restrict__ C, int M, int N, int K)
{
    extern __shared__ __align__(16) char smem[];

    const int tid = threadIdx.x;
    const int wid = tid >> 5, lane = tid & 31;
    const int gq = lane >> 2, tq = lane & 3;
    const int wm = (wid >> 2) * 64;
    const int wn = (wid & 3) * 32;
    const int bm = blockIdx.y * 128, bn = blockIdx.x * 128;
    const int nk = K >> 5;

    const __nv_bfloat16* gsrc[4] = {Ahi, Alo, Bhi, Blo};

    auto load_stage = [&](int kc) {
        char* base = smem + (kc & 1) * STG_SZ;
        int k0 = kc << 5;
#pragma unroll
        for (int i = 0; i < 8; i++) {
            int e = tid + i * 256;
            int arr = e >> 9;
            int r = (e >> 2) & 127;
            int seg = e & 3;
            int grow = (arr < 2 ? bm : bn) + r;
            const __nv_bfloat16* src = gsrc[arr] + (size_t)grow * K + k0 + seg * 8;
            cp16(base + arr * ARR_SZ + r * PITCH + seg * 16, src);
        }
        asm volatile("cp.async.commit_group;");
    };

    float acc[4][4][4];
#pragma unroll
    for (int i = 0; i < 4; i++)
#pragma unroll
        for (int j = 0; j < 4; j++)
#pragma unroll
            for (int q = 0; q < 4; q++) acc[i][j][q] = 0.f;

    load_stage(0);

    for (int kc = 0; kc < nk; kc++) {
        if (kc + 1 < nk) {
            load_stage(kc + 1);
            asm volatile("cp.async.wait_group 1;");
        } else {
            asm volatile("cp.async.wait_group 0;");
        }
        __syncthreads();

        const char* base = smem + (kc & 1) * STG_SZ;
#pragma unroll
        for (int kk = 0; kk < 2; kk++) {
            const int kb = kk * 32;
            uint32_t ah[4][4], al[4][4], bh[4][2], bl[4][2];
#pragma unroll
            for (int i = 0; i < 4; i++) {
                int r0 = wm + i * 16 + gq;
                const char* pa = base + kb + 4 * tq;
                ah[i][0] = *(const uint32_t*)(pa + OFF_AHI + r0 * PITCH);
                ah[i][1] = *(const uint32_t*)(pa + OFF_AHI + (r0 + 8) * PITCH);
                ah[i][2] = *(const uint32_t*)(pa + OFF_AHI + r0 * PITCH + 16);
                ah[i][3] = *(const uint32_t*)(pa + OFF_AHI + (r0 + 8) * PITCH + 16);
                al[i][0] = *(const uint32_t*)(pa + OFF_ALO + r0 * PITCH);
                al[i][1] = *(const uint32_t*)(pa + OFF_ALO + (r0 + 8) * PITCH);
                al[i][2] = *(const uint32_t*)(pa + OFF_ALO + r0 * PITCH + 16);
                al[i][3] = *(const uint32_t*)(pa + OFF_ALO + (r0 + 8) * PITCH + 16);
            }
#pragma unroll
            for (int j = 0; j < 4; j++) {
                int rb = wn + j * 8 + gq;
                const char* pb = base + kb + 4 * tq;
                bh[j][0] = *(const uint32_t*)(pb + OFF_BHI + rb * PITCH);
                bh[j][1] = *(const uint32_t*)(pb + OFF_BHI + rb * PITCH + 16);
                bl[j][0] = *(const uint32_t*)(pb + OFF_BLO + rb * PITCH);
                bl[j][1] = *(const uint32_t*)(pb + OFF_BLO + rb * PITCH + 16);
            }
#pragma unroll
            for (int i = 0; i < 4; i++)
#pragma unroll
                for (int j = 0; j < 4; j++) {
                    mma16816(acc[i][j], ah[i], bh[j]);
                    mma16816(acc[i][j], ah[i], bl[j]);
                    mma16816(acc[i][j], al[i], bh[j]);
                }
        }
        __syncthreads();
    }

#pragma unroll
    for (int i = 0; i < 4; i++) {
        int r0 = bm + wm + i * 16 + gq;
        if (MODE == 0) {
#pragma unroll
            for (int j = 0; j < 4; j++) {
                int col = bn + wn + j * 8 + 2 * tq;
                float b0 = bias1[col] + (bias2 ? bias2[col] : 0.f);
                float b1 = bias1[col + 1] + (bias2 ? bias2[col + 1] : 0.f);
                float2 v0 = make_float2(acc[i][j][0] + b0, acc[i][j][1] + b1);
                float2 v1 = make_float2(acc[i][j][2] + b0, acc[i][j][3] + b1);
                *(float2*)(C + (size_t)r0 * N + col) = v0;
                *(float2*)(C + (size_t)(r0 + 8) * N + col) = v1;
            }
        } else {
            float bv0 = bias1[r0];
            float bv1 = bias1[r0 + 8];
#pragma unroll
            for (int j = 0; j < 4; j++) {
                int col = bn + wn + j * 8 + 2 * tq;
                int b = col >> 5, t = col & 31;
                float* p0 = C + ((size_t)b * VD_ + r0) * 32 + t;
                float* p1 = C + ((size_t)b * VD_ + r0 + 8) * 32 + t;
                *(float2*)p0 = make_float2(acc[i][j][0] + bv0, acc[i][j][1] + bv0);
                *(float2*)p1 = make_float2(acc[i][j][2] + bv1, acc[i][j][3] + bv1);
            }
        }
    }
}

// ---------------- attention body (writes ctx as bf16 hi/lo into hc) ----------------
__device__ __forceinline__ void attn_body(int b, int ta, const float* __restrict__ ba,
                                          float* scratch)
{
    float* qs = scratch;          // 1024
    float* sc = scratch + UU;     // 65 (sc[SS] holds 1/sum)
    int tid = threadIdx.x;

    const float* qrow = g_q[ta & 1] + (size_t)b * UU;
    for (int u = tid; u < UU; u += 256) qs[u] = ba[u] + qrow[u];
    __syncthreads();

    int w = tid >> 5, lane = tid & 31;
    const float* ob = g_o + (size_t)b * SS * UU;
    for (int s = w; s < SS; s += 8) {
        const float* os = ob + (size_t)s * UU;
        float acc = 0.f;
        for (int u = lane; u < UU; u += 32) acc = fmaf(qs[u], os[u], acc);
#pragma unroll
        for (int off = 16; off; off >>= 1) acc += __shfl_xor_sync(0xffffffffu, acc, off);
        if (lane == 0) sc[s] = acc;
    }
    __syncthreads();

    if (tid == 0) {
        float mx = sc[0];
#pragma unroll
        for (int s = 1; s < SS; s++) mx = fmaxf(mx, sc[s]);
        float sum = 0.f;
        for (int s = 0; s < SS; s++) { float e = expf(sc[s] - mx); sc[s] = e; sum += e; }
        sc[SS] = 1.f / sum;
    }
    __syncthreads();
    float inv = sc[SS];

    size_t rowb = (size_t)(b * TT + ta) * U2;
    for (int u = tid; u < UU; u += 256) {
        float acc = 0.f;
#pragma unroll 8
        for (int s = 0; s < SS; s++) acc = fmaf(sc[s] * inv, ob[(size_t)s * UU + u], acc);
        __nv_bfloat16 ch, cl; split1(acc, ch, cl);
        g_hcHi[rowb + u] = ch;
        g_hcLo[rowb + u] = cl;
    }
}

// ---------------- fused recurrence step: GEMM + last-CTA reduce/gate ----------------
// MODE 0 (enc): grid 128 (32 bn x 4 ks). MODE 1 (dec): grid 224 (40x4 + 64 attn riders).
// Weight rows reordered so tile bn holds all 4 gates for a 32-u slice (dec: bn<8 = Wa/q).
// Last-arriving CTA per bn reduces the 4 K-split partials and applies the gate inline.
#define RA_SZ  (64 * PITCH)             // 5120
#define RB_SZ  (128 * PITCH)            // 10240
#define RST_SZ (2 * RA_SZ + 2 * RB_SZ)  // 30720
#define ROFF_ALO RA_SZ
#define ROFF_BHI (2 * RA_SZ)
#define ROFF_BLO (2 * RA_SZ + RB_SZ)
#define RSMEM_DYN (2 * RST_SZ)          // 61440

template <int MODE>
__global__ void __launch_bounds__(256)
k_rec_step(int t, const float* __restrict__ ba)
{
    extern __shared__ __align__(16) char smem[];

    const int tid = threadIdx.x;
    const int par = t & 1;
    constexpr int NBN = MODE ? 40 : 32;

    if (MODE == 1 && blockIdx.x >= NBN * RS) {
        // attention riders: process step t-1
        if (t > 0) attn_body(blockIdx.x - NBN * RS, t - 1, ba, (float*)smem);
        return;
    }

    const int bn = blockIdx.x >> 2, ks = blockIdx.x & 3;
    const int wid = tid >> 5, lane = tid & 31;
    const int gq = lane >> 2, tq = lane & 3;
    const int wm = (wid >> 2) * 32;               // 0,32
    const int wn = (wid & 3) * 32;                // 0..96
    const int kbase = ks * RKC;

    const __nv_bfloat16* Whi = MODE ? g_WrdHi : g_WreHi;
    const __nv_bfloat16* Wlo = MODE ? g_WrdLo : g_WreLo;
    const __nv_bfloat16* hHi = g_hHi[par];
    const __nv_bfloat16* hLo = g_hLo[par];
    const int brow = bn * 128;

    auto load_stage = [&](int kc) {
        char* base = smem + (kc & 1) * RST_SZ;
        int k0 = kbase + (kc << 5);
#pragma unroll
        for (int i = 0; i < 6; i++) {
            int e = tid + i * 256;                // 0..1535
            const __nv_bfloat16* src;
            char* dst;
            if (e < 512) {                        // A hi/lo: 64 rows x 4 segs
                int arr = e >> 8;
                int r = (e >> 2) & 63, seg = e & 3;
                src = (arr ? hLo : hHi) + (size_t)r * UU + k0 + seg * 8;
                dst = base + arr * RA_SZ + r * PITCH + seg * 16;
            } else {                              // B hi/lo: 128 rows x 4 segs
                int e2 = e - 512;
                int arr = e2 >> 9;
                int r = (e2 >> 2) & 127, seg = e2 & 3;
                src = (arr ? Wlo : Whi) + (size_t)(brow + r) * UU + k0 + seg * 8;
                dst = base + ROFF_BHI + arr * RB_SZ + r * PITCH + seg * 16;
            }
            cp16(dst, src);
        }
        asm volatile("cp.async.commit_group;");
    };

    float acc[2][4][4];
#pragma unroll
    for (int i = 0; i < 2; i++)
#pragma unroll
        for (int j = 0; j < 4; j++)
#pragma unroll
            for (int q = 0; q < 4; q++) acc[i][j][q] = 0.f;

    const int nk = RKC >> 5;                      // 8
    load_stage(0);

    for (int kc = 0; kc < nk; kc++) {
        if (kc + 1 < nk) {
            load_stage(kc + 1);
            asm volatile("cp.async.wait_group 1;");
        } else {
            asm volatile("cp.async.wait_group 0;");
        }
        __syncthreads();

        const char* base = smem + (kc & 1) * RST_SZ;
#pragma unroll
        for (int kk = 0; kk < 2; kk++) {
            const int kb = kk * 32;
            uint32_t ah[2][4], al[2][4], bh[4][2], bl[4][2];
#pragma unroll
            for (int i = 0; i < 2; i++) {
                int r0 = wm + i * 16 + gq;
                const char* pa = base + kb + 4 * tq;
                ah[i][0] = *(const uint32_t*)(pa + r0 * PITCH);
                ah[i][1] = *(const uint32_t*)(pa + (r0 + 8) * PITCH);
                ah[i][2] = *(const uint32_t*)(pa + r0 * PITCH + 16);
                ah[i][3] = *(const uint32_t*)(pa + (r0 + 8) * PITCH + 16);
                al[i][0] = *(const uint32_t*)(pa + ROFF_ALO + r0 * PITCH);
                al[i][1] = *(const uint32_t*)(pa + ROFF_ALO + (r0 + 8) * PITCH);
                al[i][2] = *(const uint32_t*)(pa + ROFF_ALO + r0 * PITCH + 16);
                al[i][3] = *(const uint32_t*)(pa + ROFF_ALO + (r0 + 8) * PITCH + 16);
            }
#pragma unroll
            for (int j = 0; j < 4; j++) {
                int rb = wn + j * 8 + gq;
                const char* pb = base + kb + 4 * tq;
                bh[j][0] = *(const uint32_t*)(pb + ROFF_BHI + rb * PITCH);
                bh[j][1] = *(const uint32_t*)(pb + ROFF_BHI + rb * PITCH + 16);
                bl[j][0] = *(const uint32_t*)(pb + ROFF_BLO + rb * PITCH);
                bl[j][1] = *(const uint32_t*)(pb + ROFF_BLO + rb * PITCH + 16);
            }
#pragma unroll
            for (int i = 0; i < 2; i++)
#pragma unroll
                for (int j = 0; j < 4; j++) {
                    mma16816(acc[i][j], ah[i], bh[j]);
                    mma16816(acc[i][j], ah[i], bl[j]);
                    mma16816(acc[i][j], al[i], bh[j]);
                }
        }
        __syncthreads();
    }

    // ---- write partial tile: g_p[bn][ks][64][128] ----
    float* P = g_p + ((size_t)(bn * RS + ks) * 64) * 128;
#pragma unroll
    for (int i = 0; i < 2; i++) {
        int r0 = wm + i * 16 + gq;
#pragma unroll
        for (int j = 0; j < 4; j++) {
            int col = wn + j * 8 + 2 * tq;
            *(float2*)(P + (size_t)r0 * 128 + col) = make_float2(acc[i][j][0], acc[i][j][1]);
            *(float2*)(P + (size_t)(r0 + 8) * 128 + col) = make_float2(acc[i][j][2], acc[i][j][3]);
        }
    }

    // ---- last-CTA-per-bn reduce + gate (threadFenceReduction pattern) ----
    __syncthreads();
    __threadfence();
    __shared__ int sLast;
    if (tid == 0) {
        int old = atomicAdd(&g_ctr[bn], 1);
        sLast = (old == RS - 1);
        if (old == RS - 1) g_ctr[bn] = 0;
    }
    __syncthreads();
    if (!sLast) return;
    __threadfence();

    const float* Pb = g_p + (size_t)bn * RS * 64 * 128;

    if (MODE == 1 && bn < 8) {
        // q reduce: q[b][bn*128+col] = sum_ks P
#pragma unroll
        for (int it = 0; it < 32; it++) {
            int item = tid + it * 256;            // 0..8191
            int b = item >> 7, col = item & 127;
            float v = Pb[(size_t)b * 128 + col];
#pragma unroll
            for (int ks2 = 1; ks2 < RS; ks2++)
                v += Pb[((size_t)ks2 * 64 + b) * 128 + col];
            g_q[par][b * UU + bn * 128 + col] = v;
        }
        return;
    }

    // gate: 64 b x 32 uu items
    const int ubase = MODE ? (bn - 8) * 32 : bn * 32;
#pragma unroll
    for (int it = 0; it < 8; it++) {
        int item = tid + it * 256;                // 0..2047
        int b = item >> 5, uu = item & 31;
        int u = ubase + uu;
        const float* xrow = MODE ? (g_Xd + (size_t)(b * TT + t) * G4)
                                 : (g_Xe + (size_t)(b * SS + t) * G4);
        float z[4];
#pragma unroll
        for (int g = 0; g < 4; g++) z[g] = xrow[g * UU + u];
#pragma unroll
        for (int ks2 = 0; ks2 < RS; ks2++)
#pragma unroll
            for (int g = 0; g < 4; g++)
                z[g] += Pb[((size_t)ks2 * 64 + b) * 128 + g * 32 + uu];

        float cprev = g_c[b * UU + u];
        float cn = sigf(z[1]) * cprev + sigf(z[0]) * tanhf(z[2]);
        float hn = sigf(z[3]) * tanhf(cn);
        g_c[b * UU + u] = cn;
        __nv_bfloat16 hh, hl; split1(hn, hh, hl);
        g_hHi[par ^ 1][b * UU + u] = hh;
        g_hLo[par ^ 1][b * UU + u] = hl;
        if (MODE == 0) {
            g_o[(size_t)(b * SS + t) * UU + u] = hn;
        } else {
            size_t row = (size_t)(b * TT + t) * U2 + UU + u;
            g_hcHi[row] = hh;
            g_hcLo[row] = hl;
        }
    }
}

__global__ void __launch_bounds__(256) k_attn_tail(int ta, const float* __restrict__ ba)
{
    __shared__ float scratch[1100];
    attn_body(blockIdx.x, ta, ba, scratch);
}

// ---------------- launch ----------------
extern "C" void kernel_launch(void* const* d_in, const int* in_sizes, int n_in,
                              void* d_out, int out_size)
{
    const int*   x       = (const int*)d_in[0];
    const int*   y       = (const int*)d_in[1];
    const float* enc_emb = (const float*)d_in[2];
    const float* dec_emb = (const float*)d_in[3];
    const float* W_ih_e  = (const float*)d_in[4];
    const float* W_hh_e  = (const float*)d_in[5];
    const float* b_ih_e  = (const float*)d_in[6];
    const float* b_hh_e  = (const float*)d_in[7];
    const float* Wa      = (const float*)d_in[8];
    const float* ba      = (const float*)d_in[9];
    const float* W_ih_d  = (const float*)d_in[10];
    const float* W_hh_d  = (const float*)d_in[11];
    const float* b_ih_d  = (const float*)d_in[12];
    const float* b_hh_d  = (const float*)d_in[13];
    const float* Wd      = (const float*)d_in[14];
    const float* bd      = (const float*)d_in[15];
    float* out = (float*)d_out;

    float *pXe, *pXd;
    __nv_bfloat16 *pXeHi, *pXeLo, *pXdHi, *pXdLo, *pWeHi, *pWeLo, *pWidHi, *pWidLo;
    __nv_bfloat16 *pWdHi, *pWdLo, *pHcHi, *pHcLo;
    cudaGetSymbolAddress((void**)&pXe, g_Xe);
    cudaGetSymbolAddress((void**)&pXd, g_Xd);
    cudaGetSymbolAddress((void**)&pXeHi, g_XembEHi);
    cudaGetSymbolAddress((void**)&pXeLo, g_XembELo);
    cudaGetSymbolAddress((void**)&pXdHi, g_XembDHi);
    cudaGetSymbolAddress((void**)&pXdLo, g_XembDLo);
    cudaGetSymbolAddress((void**)&pWeHi, g_WeHi);
    cudaGetSymbolAddress((void**)&pWeLo, g_WeLo);
    cudaGetSymbolAddress((void**)&pWidHi, g_WidHi);
    cudaGetSymbolAddress((void**)&pWidLo, g_WidLo);
    cudaGetSymbolAddress((void**)&pWdHi, g_WdHi);
    cudaGetSymbolAddress((void**)&pWdLo, g_WdLo);
    cudaGetSymbolAddress((void**)&pHcHi, g_hcHi);
    cudaGetSymbolAddress((void**)&pHcLo, g_hcLo);

    cudaFuncSetAttribute(k_hmma<0>, cudaFuncAttributeMaxDynamicSharedMemorySize, SMEM_DYN);
    cudaFuncSetAttribute(k_hmma<1>, cudaFuncAttributeMaxDynamicSharedMemorySize, SMEM_DYN);
    cudaFuncSetAttribute(k_rec_step<0>, cudaFuncAttributeMaxDynamicSharedMemorySize, RSMEM_DYN);
    cudaFuncSetAttribute(k_rec_step<1>, cudaFuncAttributeMaxDynamicSharedMemorySize, RSMEM_DYN);

    // embeddings + init + weight splits
    k_gather_enc<<<BB * SS * (EE / 4) / 256, 256>>>(x, enc_emb);
    k_gather_dec<<<BB * TT * (EE / 4) / 256, 256>>>(y, dec_emb);
    k_init_state<<<BB * UU / 256, 256>>>();
    {
        int n4 = G4 * EE / 4;
        int g = (n4 / 4 + 255) / 256;
        k_split4<<<g, 256>>>((const float4*)W_ih_e,
            (__nv_bfloat162*)pWeHi, (__nv_bfloat162*)pWeLo, n4);
        k_split4<<<g, 256>>>((const float4*)W_ih_d,
            (__nv_bfloat162*)pWidHi, (__nv_bfloat162*)pWidLo, n4);
    }
    // recurrence weights: reorder + split (gate-tiled)
    k_split_reord_enc<<<G4 * 256 / 256, 256>>>((const float4*)W_hh_e);
    k_split_reord_dec<<<(UU + G4) * 256 / 256, 256>>>((const float4*)Wa,
                                                      (const float4*)W_hh_d);
    {
        int n4 = (int)((size_t)VD_ * U2 / 4);
        int g = (n4 / 4 + 255) / 256;
        k_split4<<<g, 256>>>((const float4*)Wd,
            (__nv_bfloat162*)pWdHi, (__nv_bfloat162*)pWdLo, n4);
    }

    // time-batched input projections
    k_hmma<0><<<dim3(G4 / 128, (BB * SS) / 128), 256, SMEM_DYN>>>(
        pXeHi, pXeLo, pWeHi, pWeLo, b_ih_e, b_hh_e, pXe, BB * SS, G4, EE);
    k_hmma<0><<<dim3(G4 / 128, (BB * TT) / 128), 256, SMEM_DYN>>>(
        pXdHi, pXdLo, pWidHi, pWidLo, b_ih_d, b_hh_d, pXd, BB * TT, G4, EE);

    // encoder: ONE launch per step (GEMM + last-CTA gate)
    for (int t = 0; t < SS; t++)
        k_rec_step<0><<<32 * RS, 256, RSMEM_DYN>>>(t, ba);

    // decoder: ONE launch per step (GEMM+gate+q + attention riders for t-1)
    for (int t = 0; t < TT; t++)
        k_rec_step<1><<<40 * RS + BB, 256, RSMEM_DYN>>>(t, ba);
    k_attn_tail<<<BB, 256>>>(TT - 1, ba);

    // batched logits (A = Wd rows, B = hc rows; hc written bf16-split in the decoder)
    k_hmma<1><<<dim3((BB * TT) / 128, VD_ / 128), 256, SMEM_DYN>>>(
        pWdHi, pWdLo, pHcHi, pHcLo, bd, nullptr, out, VD_, BB * TT, U2);
}

// round 15
// speedup vs baseline: 1.5369x; 1.5369x over previous
#include <cuda_runtime.h>
#include <cuda_bf16.h>
#include <cuda_fp16.h>
#include <math.h>
#include <stdint.h>

// ---------------- problem constants ----------------
#define BB   64
#define SS   64
#define TT   32
#define EE   512
#define UU   1024
#define G4   (4*UU)      // 4096
#define U2   (2*UU)      // 2048
#define NC   (UU+G4)     // 5120 (Wa ‖ W_hh_d rows)
#define VD_  32000
#define RS   4           // recurrence K-split
#define RKC  (UU/RS)     // 256

// ---------------- device scratch (allocation-free contract) ----------------
__device__ __nv_bfloat16 g_XembEHi[BB*SS*EE];
__device__ __nv_bfloat16 g_XembELo[BB*SS*EE];
__device__ __nv_bfloat16 g_XembDHi[BB*TT*EE];
__device__ __nv_bfloat16 g_XembDLo[BB*TT*EE];
__device__ __nv_bfloat16 g_WeHi[G4*EE];
__device__ __nv_bfloat16 g_WeLo[G4*EE];
__device__ __nv_bfloat16 g_WidHi[G4*EE];
__device__ __nv_bfloat16 g_WidLo[G4*EE];
__device__ __half        g_WdH[(size_t)VD_*U2];      // fp16 Wd (single array)
__device__ __half        g_hcH[(size_t)BB*TT*U2];    // fp16 [b*T+t][ctx|h]

// recurrence bf16 weights
__device__ __nv_bfloat16 g_WhheHi[(size_t)G4*UU];
__device__ __nv_bfloat16 g_WhheLo[(size_t)G4*UU];
__device__ __nv_bfloat16 g_WcatHi[(size_t)NC*UU];     // rows 0..1023 = Wa, 1024.. = W_hh_d
__device__ __nv_bfloat16 g_WcatLo[(size_t)NC*UU];
__device__ __nv_bfloat16 g_hHi[BB*UU];
__device__ __nv_bfloat16 g_hLo[BB*UU];

__device__ float g_Xe[(size_t)BB*SS*G4];            // x@W_ih_e^T + biases
__device__ float g_Xd[(size_t)BB*TT*G4];
__device__ float g_o [(size_t)BB*SS*UU];            // encoder outputs
__device__ float g_h [BB*UU];
__device__ float g_c [BB*UU];
__device__ float g_p [(size_t)RS*BB*NC];            // K-split partials

// ---------------- helpers ----------------
__device__ __forceinline__ float sigf(float x) { return 1.f / (1.f + expf(-x)); }

__device__ __forceinline__ void cp16(void* dst, const void* src) {
    uint32_t a;
    asm("{ .reg .u64 t; cvta.to.shared.u64 t, %1; cvt.u32.u64 %0, t; }"
        : "=r"(a) : "l"(dst));
    asm volatile("cp.async.cg.shared.global [%0], [%1], 16;" :: "r"(a), "l"(src));
}

__device__ __forceinline__ void mma16816(float* c, const uint32_t* a, const uint32_t* b) {
    asm volatile(
        "mma.sync.aligned.m16n8k16.row.col.f32.bf16.bf16.f32 "
        "{%0,%1,%2,%3}, {%4,%5,%6,%7}, {%8,%9}, {%0,%1,%2,%3};"
        : "+f"(c[0]), "+f"(c[1]), "+f"(c[2]), "+f"(c[3])
        : "r"(a[0]), "r"(a[1]), "r"(a[2]), "r"(a[3]), "r"(b[0]), "r"(b[1]));
}

__device__ __forceinline__ void mma16816h(float* c, const uint32_t* a, const uint32_t* b) {
    asm volatile(
        "mma.sync.aligned.m16n8k16.row.col.f32.f16.f16.f32 "
        "{%0,%1,%2,%3}, {%4,%5,%6,%7}, {%8,%9}, {%0,%1,%2,%3};"
        : "+f"(c[0]), "+f"(c[1]), "+f"(c[2]), "+f"(c[3])
        : "r"(a[0]), "r"(a[1]), "r"(a[2]), "r"(a[3]), "r"(b[0]), "r"(b[1]));
}

__device__ __forceinline__ void split1(float x, __nv_bfloat16& h, __nv_bfloat16& l) {
    h = __float2bfloat16(x);
    l = __float2bfloat16(x - __bfloat162float(h));
}

// ---------------- fp32 -> bf16 hi/lo split ----------------
__global__ void k_split4(const float4* __restrict__ src,
                         __nv_bfloat162* __restrict__ hi,
                         __nv_bfloat162* __restrict__ lo, int n4)
{
    int base = blockIdx.x * blockDim.x + threadIdx.x;
    int stride = gridDim.x * blockDim.x;
#pragma unroll
    for (int it = 0; it < 4; it++) {
        int gid = base + it * stride;
        if (gid < n4) {
            float4 v = src[gid];
            __nv_bfloat16 hx, hy, hz, hw, lx, ly, lz, lw;
            split1(v.x, hx, lx); split1(v.y, hy, ly);
            split1(v.z, hz, lz); split1(v.w, hw, lw);
            __nv_bfloat162 a; a.x = hx; a.y = hy;
            __nv_bfloat162 b; b.x = hz; b.y = hw;
            __nv_bfloat162 c; c.x = lx; c.y = ly;
            __nv_bfloat162 d; d.x = lz; d.y = lw;
            hi[gid * 2] = a; hi[gid * 2 + 1] = b;
            lo[gid * 2] = c; lo[gid * 2 + 1] = d;
        }
    }
}

// ---------------- fp32 -> fp16 convert (for Wd) ----------------
__global__ void k_cvt_half(const float4* __restrict__ src,
                           __half2* __restrict__ dst, int n4)
{
    int gid = blockIdx.x * blockDim.x + threadIdx.x;
    if (gid >= n4) return;
    float4 v = src[gid];
    dst[gid * 2]     = __floats2half2_rn(v.x, v.y);
    dst[gid * 2 + 1] = __floats2half2_rn(v.z, v.w);
}

// ---------------- reorder + split for recurrence weights ----------------
// (identical to the proven R8/R13 layout: h@[Wa ‖ W_hh_d]^T combined)
__global__ void k_split_reord_enc_plain(const float4* __restrict__ W) {
    // plain row order for 64x128-tile K-split GEMM (no reorder needed)
    int gid = blockIdx.x * blockDim.x + threadIdx.x;   // G4 * 256
    float4 v = W[gid];
    __nv_bfloat16 hx, hy, hz, hw, lx, ly, lz, lw;
    split1(v.x, hx, lx); split1(v.y, hy, ly);
    split1(v.z, hz, lz); split1(v.w, hw, lw);
    __nv_bfloat162 a; a.x = hx; a.y = hy;
    __nv_bfloat162 b; b.x = hz; b.y = hw;
    __nv_bfloat162 cc; cc.x = lx; cc.y = ly;
    __nv_bfloat162 dd; dd.x = lz; dd.y = lw;
    ((__nv_bfloat162*)g_WhheHi)[gid * 2] = a; ((__nv_bfloat162*)g_WhheHi)[gid * 2 + 1] = b;
    ((__nv_bfloat162*)g_WhheLo)[gid * 2] = cc; ((__nv_bfloat162*)g_WhheLo)[gid * 2 + 1] = dd;
}

// ---------------- embedding gathers (write bf16 hi/lo) ----------------
__global__ void k_gather_enc(const int* __restrict__ x, const float* __restrict__ emb) {
    int gid = blockIdx.x * blockDim.x + threadIdx.x;      // BB*SS*(EE/4)
    const int E4 = EE / 4;
    int r = gid / E4, c = gid % E4;
    float4 v = ((const float4*)emb)[(size_t)x[r] * E4 + c];
    __nv_bfloat16 hx, hy, hz, hw, lx, ly, lz, lw;
    split1(v.x, hx, lx); split1(v.y, hy, ly);
    split1(v.z, hz, lz); split1(v.w, hw, lw);
    size_t pi = (size_t)r * (EE / 2) + c * 2;
    __nv_bfloat162 a; a.x = hx; a.y = hy; ((__nv_bfloat162*)g_XembEHi)[pi] = a;
    __nv_bfloat162 b; b.x = hz; b.y = hw; ((__nv_bfloat162*)g_XembEHi)[pi + 1] = b;
    __nv_bfloat162 cc; cc.x = lx; cc.y = ly; ((__nv_bfloat162*)g_XembELo)[pi] = cc;
    __nv_bfloat162 dd; dd.x = lz; dd.y = lw; ((__nv_bfloat162*)g_XembELo)[pi + 1] = dd;
}

__global__ void k_gather_dec(const int* __restrict__ y, const float* __restrict__ emb) {
    int gid = blockIdx.x * blockDim.x + threadIdx.x;      // BB*TT*(EE/4)
    const int E4 = EE / 4;
    int r = gid / E4, c = gid % E4;
    int b = r / TT, t = r % TT;
    int id = y[b * (TT + 1) + t];
    float4 v = ((const float4*)emb)[(size_t)id * E4 + c];
    __nv_bfloat16 hx, hy, hz, hw, lx, ly, lz, lw;
    split1(v.x, hx, lx); split1(v.y, hy, ly);
    split1(v.z, hz, lz); split1(v.w, hw, lw);
    size_t pi = (size_t)r * (EE / 2) + c * 2;
    __nv_bfloat162 a; a.x = hx; a.y = hy; ((__nv_bfloat162*)g_XembDHi)[pi] = a;
    __nv_bfloat162 b2; b2.x = hz; b2.y = hw; ((__nv_bfloat162*)g_XembDHi)[pi + 1] = b2;
    __nv_bfloat162 cc; cc.x = lx; cc.y = ly; ((__nv_bfloat162*)g_XembDLo)[pi] = cc;
    __nv_bfloat162 dd; dd.x = lz; dd.y = lw; ((__nv_bfloat162*)g_XembDLo)[pi + 1] = dd;
}

__global__ void k_init_state() {
    int gid = blockIdx.x * blockDim.x + threadIdx.x;
    if (gid < BB * UU) {
        g_h[gid] = 0.f; g_c[gid] = 0.f;
        g_hHi[gid] = __float2bfloat16(0.f);
        g_hLo[gid] = __float2bfloat16(0.f);
    }
}

// ---------------- HMMA bf16x2-compensated GEMM (projections, 128x128 tile) --------
#define PITCH   80
#define ARR_SZ  (128 * PITCH)           // 10240
#define STG_SZ  (4 * ARR_SZ)            // 40960
#define OFF_AHI 0
#define OFF_ALO ARR_SZ
#define OFF_BHI (2 * ARR_SZ)
#define OFF_BLO (3 * ARR_SZ)
#define SMEM_DYN (2 * STG_SZ)           // 80 KB

__global__ void __launch_bounds__(256)
k_hmma(const __nv_bfloat16* __restrict__ Ahi, const __nv_bfloat16* __restrict__ Alo,
       const __nv_bfloat16* __restrict__ Bhi, const __nv_bfloat16* __restrict__ Blo,
       const float* __restrict__ bias1, const float* __restrict__ bias2,
       float* __restrict__ C, int M, int N, int K)
{
    extern __shared__ __align__(16) char smem[];

    const int tid = threadIdx.x;
    const int wid = tid >> 5, lane = tid & 31;
    const int gq = lane >> 2, tq = lane & 3;
    const int wm = (wid >> 2) * 64;
    const int wn = (wid & 3) * 32;
    const int bm = blockIdx.y * 128, bn = blockIdx.x * 128;
    const int nk = K >> 5;

    const __nv_bfloat16* gsrc[4] = {Ahi, Alo, Bhi, Blo};

    auto load_stage = [&](int kc) {
        char* base = smem + (kc & 1) * STG_SZ;
        int k0 = kc << 5;
#pragma unroll
        for (int i = 0; i < 8; i++) {
            int e = tid + i * 256;
            int arr = e >> 9;
            int r = (e >> 2) & 127;
            int seg = e & 3;
            int grow = (arr < 2 ? bm : bn) + r;
            const __nv_bfloat16* src = gsrc[arr] + (size_t)grow * K + k0 + seg * 8;
            cp16(base + arr * ARR_SZ + r * PITCH + seg * 16, src);
        }
        asm volatile("cp.async.commit_group;");
    };

    float acc[4][4][4];
#pragma unroll
    for (int i = 0; i < 4; i++)
#pragma unroll
        for (int j = 0; j < 4; j++)
#pragma unroll
            for (int q = 0; q < 4; q++) acc[i][j][q] = 0.f;

    load_stage(0);

    for (int kc = 0; kc < nk; kc++) {
        if (kc + 1 < nk) {
            load_stage(kc + 1);
            asm volatile("cp.async.wait_group 1;");
        } else {
            asm volatile("cp.async.wait_group 0;");
        }
        __syncthreads();

        const char* base = smem + (kc & 1) * STG_SZ;
#pragma unroll
        for (int kk = 0; kk < 2; kk++) {
            const int kb = kk * 32;
            uint32_t ah[4][4], al[4][4], bh[4][2], bl[4][2];
#pragma unroll
            for (int i = 0; i < 4; i++) {
                int r0 = wm + i * 16 + gq;
                const char* pa = base + kb + 4 * tq;
                ah[i][0] = *(const uint32_t*)(pa + OFF_AHI + r0 * PITCH);
                ah[i][1] = *(const uint32_t*)(pa + OFF_AHI + (r0 + 8) * PITCH);
                ah[i][2] = *(const uint32_t*)(pa + OFF_AHI + r0 * PITCH + 16);
                ah[i][3] = *(const uint32_t*)(pa + OFF_AHI + (r0 + 8) * PITCH + 16);
                al[i][0] = *(const uint32_t*)(pa + OFF_ALO + r0 * PITCH);
                al[i][1] = *(const uint32_t*)(pa + OFF_ALO + (r0 + 8) * PITCH);
                al[i][2] = *(const uint32_t*)(pa + OFF_ALO + r0 * PITCH + 16);
                al[i][3] = *(const uint32_t*)(pa + OFF_ALO + (r0 + 8) * PITCH + 16);
            }
#pragma unroll
            for (int j = 0; j < 4; j++) {
                int rb = wn + j * 8 + gq;
                const char* pb = base + kb + 4 * tq;
                bh[j][0] = *(const uint32_t*)(pb + OFF_BHI + rb * PITCH);
                bh[j][1] = *(const uint32_t*)(pb + OFF_BHI + rb * PITCH + 16);
                bl[j][0] = *(const uint32_t*)(pb + OFF_BLO + rb * PITCH);
                bl[j][1] = *(const uint32_t*)(pb + OFF_BLO + rb * PITCH + 16);
            }
#pragma unroll
            for (int i = 0; i < 4; i++)
#pragma unroll
                for (int j = 0; j < 4; j++) {
                    mma16816(acc[i][j], ah[i], bh[j]);
                    mma16816(acc[i][j], ah[i], bl[j]);
                    mma16816(acc[i][j], al[i], bh[j]);
                }
        }
        __syncthreads();
    }

#pragma unroll
    for (int i = 0; i < 4; i++) {
        int r0 = bm + wm + i * 16 + gq;
#pragma unroll
        for (int j = 0; j < 4; j++) {
            int col = bn + wn + j * 8 + 2 * tq;
            float b0 = bias1[col] + (bias2 ? bias2[col] : 0.f);
            float b1 = bias1[col + 1] + (bias2 ? bias2[col + 1] : 0.f);
            float2 v0 = make_float2(acc[i][j][0] + b0, acc[i][j][1] + b1);
            float2 v1 = make_float2(acc[i][j][2] + b0, acc[i][j][3] + b1);
            *(float2*)(C + (size_t)r0 * N + col) = v0;
            *(float2*)(C + (size_t)(r0 + 8) * N + col) = v1;
        }
    }
}

// ---------------- fp16 single-pass logits GEMM ----------------
// C[(b*VD + m)*32 + t] = Wd[m] . hc[b*32+t] + bd[m];  A=Wd fp16, B=hc fp16.
#define HA_OFF 0
#define HB_OFF (128 * PITCH)
#define HSTG   (2 * 128 * PITCH)        // 20480 per stage

__global__ void __launch_bounds__(256)
k_hmma_f16(const __half* __restrict__ A, const __half* __restrict__ B,
           const float* __restrict__ bias1, float* __restrict__ C,
           int M, int N, int K)
{
    __shared__ __align__(16) char smem[2 * HSTG];   // 40 KB

    const int tid = threadIdx.x;
    const int wid = tid >> 5, lane = tid & 31;
    const int gq = lane >> 2, tq = lane & 3;
    const int wm = (wid >> 2) * 64;
    const int wn = (wid & 3) * 32;
    const int bm = blockIdx.y * 128, bn = blockIdx.x * 128;
    const int nk = K >> 5;

    auto load_stage = [&](int kc) {
        char* base = smem + (kc & 1) * HSTG;
        int k0 = kc << 5;
#pragma unroll
        for (int i = 0; i < 4; i++) {
            int e = tid + i * 256;
            int arr = e >> 9;
            int r = (e >> 2) & 127;
            int seg = e & 3;
            const __half* src = (arr ? B + (size_t)(bn + r) * K
                                     : A + (size_t)(bm + r) * K) + k0 + seg * 8;
            cp16(base + arr * (128 * PITCH) + r * PITCH + seg * 16, src);
        }
        asm volatile("cp.async.commit_group;");
    };

    float acc[4][4][4];
#pragma unroll
    for (int i = 0; i < 4; i++)
#pragma unroll
        for (int j = 0; j < 4; j++)
#pragma unroll
            for (int q = 0; q < 4; q++) acc[i][j][q] = 0.f;

    load_stage(0);

    for (int kc = 0; kc < nk; kc++) {
        if (kc + 1 < nk) {
            load_stage(kc + 1);
            asm volatile("cp.async.wait_group 1;");
        } else {
            asm volatile("cp.async.wait_group 0;");
        }
        __syncthreads();

        const char* base = smem + (kc & 1) * HSTG;
#pragma unroll
        for (int kk = 0; kk < 2; kk++) {
            const int kb = kk * 32;
            uint32_t ah[4][4], bh[4][2];
#pragma unroll
            for (int i = 0; i < 4; i++) {
                int r0 = wm + i * 16 + gq;
                const char* pa = base + HA_OFF + kb + 4 * tq;
                ah[i][0] = *(const uint32_t*)(pa + r0 * PITCH);
                ah[i][1] = *(const uint32_t*)(pa + (r0 + 8) * PITCH);
                ah[i][2] = *(const uint32_t*)(pa + r0 * PITCH + 16);
                ah[i][3] = *(const uint32_t*)(pa + (r0 + 8) * PITCH + 16);
            }
#pragma unroll
            for (int j = 0; j < 4; j++) {
                int rb = wn + j * 8 + gq;
                const char* pb = base + HB_OFF + kb + 4 * tq;
                bh[j][0] = *(const uint32_t*)(pb + rb * PITCH);
                bh[j][1] = *(const uint32_t*)(pb + rb * PITCH + 16);
            }
#pragma unroll
            for (int i = 0; i < 4; i++)
#pragma unroll
                for (int j = 0; j < 4; j++)
                    mma16816h(acc[i][j], ah[i], bh[j]);
        }
        __syncthreads();
    }

#pragma unroll
    for (int i = 0; i < 4; i++) {
        int r0 = bm + wm + i * 16 + gq;
        float bv0 = bias1[r0];
        float bv1 = bias1[r0 + 8];
#pragma unroll
        for (int j = 0; j < 4; j++) {
            int col = bn + wn + j * 8 + 2 * tq;
            int b = col >> 5, t = col & 31;
            float* p0 = C + ((size_t)b * VD_ + r0) * 32 + t;
            float* p1 = C + ((size_t)b * VD_ + r0 + 8) * 32 + t;
            *(float2*)p0 = make_float2(acc[i][j][0] + bv0, acc[i][j][1] + bv0);
            *(float2*)p1 = make_float2(acc[i][j][2] + bv1, acc[i][j][3] + bv1);
        }
    }
}

// ---------------- HMMA recurrence GEMM: P[ks][64][N] = h[64,1024]@W[N,1024]^T chunk ----
#define RA_SZ  (64 * PITCH)             // 5120
#define RB_SZ  (128 * PITCH)            // 10240
#define RST_SZ (2 * RA_SZ + 2 * RB_SZ)  // 30720
#define ROFF_ALO RA_SZ
#define ROFF_BHI (2 * RA_SZ)
#define ROFF_BLO (2 * RA_SZ + RB_SZ)
#define RSMEM_DYN (2 * RST_SZ)          // 61440

__global__ void __launch_bounds__(256)
k_hmma_rec(const __nv_bfloat16* __restrict__ Ahi, const __nv_bfloat16* __restrict__ Alo,
           const __nv_bfloat16* __restrict__ Bhi, const __nv_bfloat16* __restrict__ Blo,
           float* __restrict__ P, int N)
{
    extern __shared__ __align__(16) char smem[];

    const int tid = threadIdx.x;
    const int wid = tid >> 5, lane = tid & 31;
    const int gq = lane >> 2, tq = lane & 3;
    const int wm = (wid >> 2) * 32;               // 0,32
    const int wn = (wid & 3) * 32;                // 0..96
    const int bn = blockIdx.x * 128;
    const int ks = blockIdx.y;
    const int kbase = ks * RKC;

    auto load_stage = [&](int kc) {
        char* base = smem + (kc & 1) * RST_SZ;
        int k0 = kbase + (kc << 5);
#pragma unroll
        for (int i = 0; i < 6; i++) {
            int e = tid + i * 256;                // 0..1535
            const __nv_bfloat16* src;
            char* dst;
            if (e < 512) {                        // A hi/lo: 64 rows x 4 segs
                int arr = e >> 8;
                int r = (e >> 2) & 63, seg = e & 3;
                src = (arr ? Alo : Ahi) + (size_t)r * UU + k0 + seg * 8;
                dst = base + arr * RA_SZ + r * PITCH + seg * 16;
            } else {                              // B hi/lo: 128 rows x 4 segs
                int e2 = e - 512;
                int arr = e2 >> 9;
                int r = (e2 >> 2) & 127, seg = e2 & 3;
                src = (arr ? Blo : Bhi) + (size_t)(bn + r) * UU + k0 + seg * 8;
                dst = base + ROFF_BHI + arr * RB_SZ + r * PITCH + seg * 16;
            }
            cp16(dst, src);
        }
        asm volatile("cp.async.commit_group;");
    };

    float acc[2][4][4];
#pragma unroll
    for (int i = 0; i < 2; i++)
#pragma unroll
        for (int j = 0; j < 4; j++)
#pragma unroll
            for (int q = 0; q < 4; q++) acc[i][j][q] = 0.f;

    const int nk = RKC >> 5;                      // 8
    load_stage(0);

    for (int kc = 0; kc < nk; kc++) {
        if (kc + 1 < nk) {
            load_stage(kc + 1);
            asm volatile("cp.async.wait_group 1;");
        } else {
            asm volatile("cp.async.wait_group 0;");
        }
        __syncthreads();

        const char* base = smem + (kc & 1) * RST_SZ;
#pragma unroll
        for (int kk = 0; kk < 2; kk++) {
            const int kb = kk * 32;
            uint32_t ah[2][4], al[2][4], bh[4][2], bl[4][2];
#pragma unroll
            for (int i = 0; i < 2; i++) {
                int r0 = wm + i * 16 + gq;
                const char* pa = base + kb + 4 * tq;
                ah[i][0] = *(const uint32_t*)(pa + r0 * PITCH);
                ah[i][1] = *(const uint32_t*)(pa + (r0 + 8) * PITCH);
                ah[i][2] = *(const uint32_t*)(pa + r0 * PITCH + 16);
                ah[i][3] = *(const uint32_t*)(pa + (r0 + 8) * PITCH + 16);
                al[i][0] = *(const uint32_t*)(pa + ROFF_ALO + r0 * PITCH);
                al[i][1] = *(const uint32_t*)(pa + ROFF_ALO + (r0 + 8) * PITCH);
                al[i][2] = *(const uint32_t*)(pa + ROFF_ALO + r0 * PITCH + 16);
                al[i][3] = *(const uint32_t*)(pa + ROFF_ALO + (r0 + 8) * PITCH + 16);
            }
#pragma unroll
            for (int j = 0; j < 4; j++) {
                int rb = wn + j * 8 + gq;
                const char* pb = base + kb + 4 * tq;
                bh[j][0] = *(const uint32_t*)(pb + ROFF_BHI + rb * PITCH);
                bh[j][1] = *(const uint32_t*)(pb + ROFF_BHI + rb * PITCH + 16);
                bl[j][0] = *(const uint32_t*)(pb + ROFF_BLO + rb * PITCH);
                bl[j][1] = *(const uint32_t*)(pb + ROFF_BLO + rb * PITCH + 16);
            }
#pragma unroll
            for (int i = 0; i < 2; i++)
#pragma unroll
                for (int j = 0; j < 4; j++) {
                    mma16816(acc[i][j], ah[i], bh[j]);
                    mma16816(acc[i][j], ah[i], bl[j]);
                    mma16816(acc[i][j], al[i], bh[j]);
                }
        }
        __syncthreads();
    }

#pragma unroll
    for (int i = 0; i < 2; i++) {
        int r0 = wm + i * 16 + gq;
#pragma unroll
        for (int j = 0; j < 4; j++) {
            int col = bn + wn + j * 8 + 2 * tq;
            float* p0 = P + ((size_t)(ks * BB) + r0) * N + col;
            float* p1 = P + ((size_t)(ks * BB) + r0 + 8) * N + col;
            *(float2*)p0 = make_float2(acc[i][j][0], acc[i][j][1]);
            *(float2*)p1 = make_float2(acc[i][j][2], acc[i][j][3]);
        }
    }
}

// ---------------- encoder LSTM pointwise step ----------------
__global__ void k_enc_gate(int t)
{
    int gid = blockIdx.x * blockDim.x + threadIdx.x;
    int b = gid >> 10, u = gid & 1023;
    const float* xe = g_Xe + (size_t)(b * SS + t) * G4;
    float z[4];
#pragma unroll
    for (int gI = 0; gI < 4; gI++) {
        int col = gI * UU + u;
        float v = xe[col];
#pragma unroll
        for (int ks = 0; ks < RS; ks++) v += g_p[((size_t)ks * BB + b) * G4 + col];
        z[gI] = v;
    }
    float cprev = g_c[gid];
    float cn = sigf(z[1]) * cprev + sigf(z[0]) * tanhf(z[2]);
    float hn = sigf(z[3]) * tanhf(cn);
    g_c[gid] = cn;
    g_h[gid] = hn;
    __nv_bfloat16 hh, hl; split1(hn, hh, hl);
    g_hHi[gid] = hh; g_hLo[gid] = hl;
    g_o[(size_t)(b * SS + t) * UU + u] = hn;
}

// ---------------- fused decoder step: attention (blocks 0..63) + gate (blocks 64..319) ----
__global__ void __launch_bounds__(256)
k_dec_fused(int t, const float* __restrict__ ba)
{
    __shared__ float qs[UU];
    __shared__ float sc[SS];
    __shared__ float sinv;

    int tid = threadIdx.x;

    if (blockIdx.x < BB) {
        // ---------- attention for batch b (ctx -> hc fp16 directly) ----------
        int b = blockIdx.x;
        for (int u = tid; u < UU; u += 256) {
            float v = ba[u];
#pragma unroll
            for (int ks = 0; ks < RS; ks++) v += g_p[((size_t)ks * BB + b) * NC + u];
            qs[u] = v;
        }
        __syncthreads();

        int w = tid >> 5, lane = tid & 31;
        const float* ob = g_o + (size_t)b * SS * UU;
        for (int s = w; s < SS; s += 8) {
            const float* os = ob + (size_t)s * UU;
            float acc = 0.f;
            for (int u = lane; u < UU; u += 32) acc = fmaf(qs[u], os[u], acc);
#pragma unroll
            for (int off = 16; off; off >>= 1) acc += __shfl_xor_sync(0xffffffffu, acc, off);
            if (lane == 0) sc[s] = acc;
        }
        __syncthreads();

        if (tid == 0) {
            float mx = sc[0];
#pragma unroll
            for (int s = 1; s < SS; s++) mx = fmaxf(mx, sc[s]);
            float sum = 0.f;
            for (int s = 0; s < SS; s++) { float e = expf(sc[s] - mx); sc[s] = e; sum += e; }
            sinv = 1.f / sum;
        }
        __syncthreads();
        float inv = sinv;

        size_t rowb = (size_t)(b * TT + t) * U2;
        for (int u = tid; u < UU; u += 256) {
            float acc = 0.f;
#pragma unroll 8
            for (int s = 0; s < SS; s++) acc = fmaf(sc[s] * inv, ob[(size_t)s * UU + u], acc);
            g_hcH[rowb + u] = __float2half(acc);
        }
    } else {
        // ---------- LSTM gate (h -> hc fp16 directly) ----------
        int gid = (blockIdx.x - BB) * 256 + tid;     // 0 .. B*U-1
        int b = gid >> 10, u = gid & 1023;
        const float* xd = g_Xd + (size_t)(b * TT + t) * G4;
        float z[4];
#pragma unroll
        for (int gI = 0; gI < 4; gI++) {
            int col = UU + gI * UU + u;              // z block sits after q block
#pragma unroll
            for (int ks = 0; ks < RS; ks++)
                z[gI] = (ks == 0 ? xd[gI * UU + u] : z[gI]) + g_p[((size_t)ks * BB + b) * NC + col];
        }
        float cprev = g_c[gid];
        float cn = sigf(z[1]) * cprev + sigf(z[0]) * tanhf(z[2]);
        float hn = sigf(z[3]) * tanhf(cn);
        g_c[gid] = cn;
        g_h[gid] = hn;
        __nv_bfloat16 hh, hl; split1(hn, hh, hl);
        g_hHi[gid] = hh; g_hLo[gid] = hl;
        g_hcH[(size_t)(b * TT + t) * U2 + UU + u] = __float2half(hn);
    }
}

// ---------------- launch ----------------
extern "C" void kernel_launch(void* const* d_in, const int* in_sizes, int n_in,
                              void* d_out, int out_size)
{
    const int*   x       = (const int*)d_in[0];
    const int*   y       = (const int*)d_in[1];
    const float* enc_emb = (const float*)d_in[2];
    const float* dec_emb = (const float*)d_in[3];
    const float* W_ih_e  = (const float*)d_in[4];
    const float* W_hh_e  = (const float*)d_in[5];
    const float* b_ih_e  = (const float*)d_in[6];
    const float* b_hh_e  = (const float*)d_in[7];
    const float* Wa      = (const float*)d_in[8];
    const float* ba      = (const float*)d_in[9];
    const float* W_ih_d  = (const float*)d_in[10];
    const float* W_hh_d  = (const float*)d_in[11];
    const float* b_ih_d  = (const float*)d_in[12];
    const float* b_hh_d  = (const float*)d_in[13];
    const float* Wd      = (const float*)d_in[14];
    const float* bd      = (const float*)d_in[15];
    float* out = (float*)d_out;

    float *pXe, *pXd, *pP;
    __nv_bfloat16 *pXeHi, *pXeLo, *pXdHi, *pXdLo, *pWeHi, *pWeLo, *pWidHi, *pWidLo;
    __nv_bfloat16 *pWhheHi, *pWhheLo, *pWcatHi, *pWcatLo, *pHHi, *pHLo;
    __half *pWdH, *pHcH;
    cudaGetSymbolAddress((void**)&pXe, g_Xe);
    cudaGetSymbolAddress((void**)&pXd, g_Xd);
    cudaGetSymbolAddress((void**)&pP,  g_p);
    cudaGetSymbolAddress((void**)&pXeHi, g_XembEHi);
    cudaGetSymbolAddress((void**)&pXeLo, g_XembELo);
    cudaGetSymbolAddress((void**)&pXdHi, g_XembDHi);
    cudaGetSymbolAddress((void**)&pXdLo, g_XembDLo);
    cudaGetSymbolAddress((void**)&pWeHi, g_WeHi);
    cudaGetSymbolAddress((void**)&pWeLo, g_WeLo);
    cudaGetSymbolAddress((void**)&pWidHi, g_WidHi);
    cudaGetSymbolAddress((void**)&pWidLo, g_WidLo);
    cudaGetSymbolAddress((void**)&pWdH, g_WdH);
    cudaGetSymbolAddress((void**)&pHcH, g_hcH);
    cudaGetSymbolAddress((void**)&pWhheHi, g_WhheHi);
    cudaGetSymbolAddress((void**)&pWhheLo, g_WhheLo);
    cudaGetSymbolAddress((void**)&pWcatHi, g_WcatHi);
    cudaGetSymbolAddress((void**)&pWcatLo, g_WcatLo);
    cudaGetSymbolAddress((void**)&pHHi, g_hHi);
    cudaGetSymbolAddress((void**)&pHLo, g_hLo);

    cudaFuncSetAttribute(k_hmma, cudaFuncAttributeMaxDynamicSharedMemorySize, SMEM_DYN);
    cudaFuncSetAttribute(k_hmma_rec, cudaFuncAttributeMaxDynamicSharedMemorySize, RSMEM_DYN);

    // embeddings + init + weight splits
    k_gather_enc<<<BB * SS * (EE / 4) / 256, 256>>>(x, enc_emb);
    k_gather_dec<<<BB * TT * (EE / 4) / 256, 256>>>(y, dec_emb);
    k_init_state<<<BB * UU / 256, 256>>>();
    {
        int n4 = G4 * EE / 4;
        int g = (n4 / 4 + 255) / 256;
        k_split4<<<g, 256>>>((const float4*)W_ih_e,
            (__nv_bfloat162*)pWeHi, (__nv_bfloat162*)pWeLo, n4);
        k_split4<<<g, 256>>>((const float4*)W_ih_d,
            (__nv_bfloat162*)pWidHi, (__nv_bfloat162*)pWidLo, n4);
    }
    {   // recurrence weights: W_hh_e ; [Wa ; W_hh_d] concatenated
        k_split_reord_enc_plain<<<G4 * 256 / 256, 256>>>((const float4*)W_hh_e);
        int n4a = UU * UU / 4;
        int ga = (n4a / 4 + 255) / 256;
        k_split4<<<ga, 256>>>((const float4*)Wa,
            (__nv_bfloat162*)pWcatHi, (__nv_bfloat162*)pWcatLo, n4a);
        int n4d = G4 * UU / 4;
        int gd = (n4d / 4 + 255) / 256;
        k_split4<<<gd, 256>>>((const float4*)W_hh_d,
            (__nv_bfloat162*)(pWcatHi + (size_t)UU * UU),
            (__nv_bfloat162*)(pWcatLo + (size_t)UU * UU), n4d);
    }
    {   // Wd: single fp16 convert
        int n4 = (int)((size_t)VD_ * U2 / 4);
        k_cvt_half<<<(n4 + 255) / 256, 256>>>((const float4*)Wd, (__half2*)pWdH, n4);
    }

    // time-batched input projections (3-pass bf16)
    k_hmma<<<dim3(G4 / 128, (BB * SS) / 128), 256, SMEM_DYN>>>(
        pXeHi, pXeLo, pWeHi, pWeLo, b_ih_e, b_hh_e, pXe, BB * SS, G4, EE);
    k_hmma<<<dim3(G4 / 128, (BB * TT) / 128), 256, SMEM_DYN>>>(
        pXdHi, pXdLo, pWidHi, pWidLo, b_ih_d, b_hh_d, pXd, BB * TT, G4, EE);

    // encoder recurrence (tensor pipe, proven R13 structure)
    for (int t = 0; t < SS; t++) {
        k_hmma_rec<<<dim3(G4 / 128, RS), 256, RSMEM_DYN>>>(
            pHHi, pHLo, pWhheHi, pWhheLo, pP, G4);
        k_enc_gate<<<BB * UU / 256, 256>>>(t);
    }

    // decoder recurrence: one combined GEMM (q ‖ z) + one fused attn/gate kernel per step
    for (int t = 0; t < TT; t++) {
        k_hmma_rec<<<dim3(NC / 128, RS), 256, RSMEM_DYN>>>(
            pHHi, pHLo, pWcatHi, pWcatLo, pP, NC);
        k_dec_fused<<<BB + BB * UU / 256, 256>>>(t, ba);
    }

    // batched logits: single-pass fp16 (A = Wd rows, B = hc rows)
    k_hmma_f16<<<dim3((BB * TT) / 128, VD_ / 128), 256>>>(
        pWdH, pHcH, bd, out, VD_, BB * TT, U2);
}

// round 16
// speedup vs baseline: 1.7702x; 1.1518x over previous
#include <cuda_runtime.h>
#include <cuda_fp16.h>
#include <math.h>
#include <stdint.h>

// ---------------- problem constants ----------------
#define BB   64
#define SS   64
#define TT   32
#define EE   512
#define UU   1024
#define G4   (4*UU)      // 4096
#define U2   (2*UU)      // 2048
#define NC   (UU+G4)     // 5120 (Wa ‖ W_hh_d rows)
#define VD_  32000
#define RS   4           // recurrence K-split
#define RKC  (UU/RS)     // 256

// ---------------- device scratch (allocation-free contract) ----------------
__device__ __half g_XembEH[(size_t)BB*SS*EE];
__device__ __half g_XembDH[(size_t)BB*TT*EE];
__device__ __half g_WeH [(size_t)G4*EE];
__device__ __half g_WidH[(size_t)G4*EE];
__device__ __half g_WdH [(size_t)VD_*U2];
__device__ __half g_hcH [(size_t)BB*TT*U2];       // fp16 [b*T+t][ctx|h]

// recurrence fp16 weights + fp16 hi/lo h state
__device__ __half g_WhheH[(size_t)G4*UU];
__device__ __half g_WcatH[(size_t)NC*UU];         // rows 0..1023 = Wa, 1024.. = W_hh_d
__device__ __half g_hHi[BB*UU];
__device__ __half g_hLo[BB*UU];

__device__ float g_Xe[(size_t)BB*SS*G4];          // x@W_ih_e^T + biases
__device__ float g_Xd[(size_t)BB*TT*G4];
__device__ float g_o [(size_t)BB*SS*UU];          // encoder outputs (fp32)
__device__ float g_c [BB*UU];
__device__ float g_p [(size_t)RS*BB*NC];          // K-split partials

// ---------------- helpers ----------------
__device__ __forceinline__ float sigf(float x) { return 1.f / (1.f + expf(-x)); }

__device__ __forceinline__ void cp16(void* dst, const void* src) {
    uint32_t a;
    asm("{ .reg .u64 t; cvta.to.shared.u64 t, %1; cvt.u32.u64 %0, t; }"
        : "=r"(a) : "l"(dst));
    asm volatile("cp.async.cg.shared.global [%0], [%1], 16;" :: "r"(a), "l"(src));
}

__device__ __forceinline__ void mma16816h(float* c, const uint32_t* a, const uint32_t* b) {
    asm volatile(
        "mma.sync.aligned.m16n8k16.row.col.f32.f16.f16.f32 "
        "{%0,%1,%2,%3}, {%4,%5,%6,%7}, {%8,%9}, {%0,%1,%2,%3};"
        : "+f"(c[0]), "+f"(c[1]), "+f"(c[2]), "+f"(c[3])
        : "r"(a[0]), "r"(a[1]), "r"(a[2]), "r"(a[3]), "r"(b[0]), "r"(b[1]));
}

__device__ __forceinline__ void split1h(float x, __half& h, __half& l) {
    h = __float2half(x);
    l = __float2half(x - __half2float(h));
}

// ---------------- fp32 -> fp16 convert ----------------
__global__ void k_cvt_half(const float4* __restrict__ src,
                           __half2* __restrict__ dst, int n4)
{
    int gid = blockIdx.x * blockDim.x + threadIdx.x;
    if (gid >= n4) return;
    float4 v = src[gid];
    dst[gid * 2]     = __floats2half2_rn(v.x, v.y);
    dst[gid * 2 + 1] = __floats2half2_rn(v.z, v.w);
}

// ---------------- embedding gathers (write fp16) ----------------
__global__ void k_gather_enc(const int* __restrict__ x, const float* __restrict__ emb) {
    int gid = blockIdx.x * blockDim.x + threadIdx.x;      // BB*SS*(EE/4)
    const int E4 = EE / 4;
    int r = gid / E4, c = gid % E4;
    float4 v = ((const float4*)emb)[(size_t)x[r] * E4 + c];
    ((__half2*)g_XembEH)[gid * 2]     = __floats2half2_rn(v.x, v.y);
    ((__half2*)g_XembEH)[gid * 2 + 1] = __floats2half2_rn(v.z, v.w);
}

__global__ void k_gather_dec(const int* __restrict__ y, const float* __restrict__ emb) {
    int gid = blockIdx.x * blockDim.x + threadIdx.x;      // BB*TT*(EE/4)
    const int E4 = EE / 4;
    int r = gid / E4, c = gid % E4;
    int b = r / TT, t = r % TT;
    int id = y[b * (TT + 1) + t];
    float4 v = ((const float4*)emb)[(size_t)id * E4 + c];
    ((__half2*)g_XembDH)[gid * 2]     = __floats2half2_rn(v.x, v.y);
    ((__half2*)g_XembDH)[gid * 2 + 1] = __floats2half2_rn(v.z, v.w);
}

__global__ void k_init_state() {
    int gid = blockIdx.x * blockDim.x + threadIdx.x;
    if (gid < BB * UU) {
        g_c[gid] = 0.f;
        g_hHi[gid] = __float2half(0.f);
        g_hLo[gid] = __float2half(0.f);
    }
}

// ---------------- fp16 single-pass GEMM (projections + logits), 128x128 tile ------
// MODE 0: C[m*N+n] = A[m].B[n] + bias1[n] + bias2[n]   (A=Xemb, B=W_ih)
// MODE 1: C[((n>>5)*VD + m)*32 + (n&31)] = A[m].B[n] + bias1[m]  (A=Wd, B=hc)
#define PITCH   80
#define HARR    (128 * PITCH)           // 10240
#define HSTG    (2 * HARR)              // 20480 per stage

template <int MODE>
__global__ void __launch_bounds__(256)
k_hf16(const __half* __restrict__ A, const __half* __restrict__ B,
       const float* __restrict__ bias1, const float* __restrict__ bias2,
       float* __restrict__ C, int M, int N, int K)
{
    __shared__ __align__(16) char smem[2 * HSTG];   // 40 KB

    const int tid = threadIdx.x;
    const int wid = tid >> 5, lane = tid & 31;
    const int gq = lane >> 2, tq = lane & 3;
    const int wm = (wid >> 2) * 64;
    const int wn = (wid & 3) * 32;
    const int bm = blockIdx.y * 128, bn = blockIdx.x * 128;
    const int nk = K >> 5;

    auto load_stage = [&](int kc) {
        char* base = smem + (kc & 1) * HSTG;
        int k0 = kc << 5;
#pragma unroll
        for (int i = 0; i < 4; i++) {
            int e = tid + i * 256;
            int arr = e >> 9;
            int r = (e >> 2) & 127;
            int seg = e & 3;
            const __half* src = (arr ? B + (size_t)(bn + r) * K
                                     : A + (size_t)(bm + r) * K) + k0 + seg * 8;
            cp16(base + arr * HARR + r * PITCH + seg * 16, src);
        }
        asm volatile("cp.async.commit_group;");
    };

    float acc[4][4][4];
#pragma unroll
    for (int i = 0; i < 4; i++)
#pragma unroll
        for (int j = 0; j < 4; j++)
#pragma unroll
            for (int q = 0; q < 4; q++) acc[i][j][q] = 0.f;

    load_stage(0);

    for (int kc = 0; kc < nk; kc++) {
        if (kc + 1 < nk) {
            load_stage(kc + 1);
            asm volatile("cp.async.wait_group 1;");
        } else {
            asm volatile("cp.async.wait_group 0;");
        }
        __syncthreads();

        const char* base = smem + (kc & 1) * HSTG;
#pragma unroll
        for (int kk = 0; kk < 2; kk++) {
            const int kb = kk * 32;
            uint32_t ah[4][4], bh[4][2];
#pragma unroll
            for (int i = 0; i < 4; i++) {
                int r0 = wm + i * 16 + gq;
                const char* pa = base + kb + 4 * tq;
                ah[i][0] = *(const uint32_t*)(pa + r0 * PITCH);
                ah[i][1] = *(const uint32_t*)(pa + (r0 + 8) * PITCH);
                ah[i][2] = *(const uint32_t*)(pa + r0 * PITCH + 16);
                ah[i][3] = *(const uint32_t*)(pa + (r0 + 8) * PITCH + 16);
            }
#pragma unroll
            for (int j = 0; j < 4; j++) {
                int rb = wn + j * 8 + gq;
                const char* pb = base + HARR + kb + 4 * tq;
                bh[j][0] = *(const uint32_t*)(pb + rb * PITCH);
                bh[j][1] = *(const uint32_t*)(pb + rb * PITCH + 16);
            }
#pragma unroll
            for (int i = 0; i < 4; i++)
#pragma unroll
                for (int j = 0; j < 4; j++)
                    mma16816h(acc[i][j], ah[i], bh[j]);
        }
        __syncthreads();
    }

#pragma unroll
    for (int i = 0; i < 4; i++) {
        int r0 = bm + wm + i * 16 + gq;
        if (MODE == 0) {
#pragma unroll
            for (int j = 0; j < 4; j++) {
                int col = bn + wn + j * 8 + 2 * tq;
                float b0 = bias1[col] + bias2[col];
                float b1 = bias1[col + 1] + bias2[col + 1];
                float2 v0 = make_float2(acc[i][j][0] + b0, acc[i][j][1] + b1);
                float2 v1 = make_float2(acc[i][j][2] + b0, acc[i][j][3] + b1);
                *(float2*)(C + (size_t)r0 * N + col) = v0;
                *(float2*)(C + (size_t)(r0 + 8) * N + col) = v1;
            }
        } else {
            float bv0 = bias1[r0];
            float bv1 = bias1[r0 + 8];
#pragma unroll
            for (int j = 0; j < 4; j++) {
                int col = bn + wn + j * 8 + 2 * tq;
                int b = col >> 5, t = col & 31;
                float* p0 = C + ((size_t)b * VD_ + r0) * 32 + t;
                float* p1 = C + ((size_t)b * VD_ + r0 + 8) * 32 + t;
                *(float2*)p0 = make_float2(acc[i][j][0] + bv0, acc[i][j][1] + bv0);
                *(float2*)p1 = make_float2(acc[i][j][2] + bv1, acc[i][j][3] + bv1);
            }
        }
    }
}

// ---------------- fp16 2-pass recurrence GEMM ----------------
// P[ks][64][N] = (hHi+hLo)[64,1024] @ W[N,1024]^T (K chunk ks), fp32 accum.
// 64x128 tile, BK=32, 8 warps (2x4), warp tile 32x32. A = h hi/lo fp16, B = W fp16.
#define FA_SZ  (64 * PITCH)             // 5120
#define FB_OFF (2 * FA_SZ)              // 10240
#define FST    (2 * FA_SZ + 128 * PITCH)   // 20480 per stage

__global__ void __launch_bounds__(256)
k_rec_f16(const __half* __restrict__ W, float* __restrict__ P, int N)
{
    __shared__ __align__(16) char smem[2 * FST];    // 40 KB

    const int tid = threadIdx.x;
    const int wid = tid >> 5, lane = tid & 31;
    const int gq = lane >> 2, tq = lane & 3;
    const int wm = (wid >> 2) * 32;               // 0,32
    const int wn = (wid & 3) * 32;                // 0..96
    const int bn = blockIdx.x * 128;
    const int ks = blockIdx.y;
    const int kbase = ks * RKC;

    auto load_stage = [&](int kc) {
        char* base = smem + (kc & 1) * FST;
        int k0 = kbase + (kc << 5);
#pragma unroll
        for (int i = 0; i < 4; i++) {
            int e = tid + i * 256;                // 0..1023
            const __half* src;
            char* dst;
            if (e < 512) {                        // A hi/lo: 64 rows x 4 segs x 2
                int arr = e >> 8;
                int r = (e >> 2) & 63, seg = e & 3;
                src = (arr ? g_hLo : g_hHi) + (size_t)r * UU + k0 + seg * 8;
                dst = base + arr * FA_SZ + r * PITCH + seg * 16;
            } else {                              // B: 128 rows x 4 segs
                int e2 = e - 512;
                int r = (e2 >> 2) & 127, seg = e2 & 3;
                src = W + (size_t)(bn + r) * UU + k0 + seg * 8;
                dst = base + FB_OFF + r * PITCH + seg * 16;
            }
            cp16(dst, src);
        }
        asm volatile("cp.async.commit_group;");
    };

    float acc[2][4][4];
#pragma unroll
    for (int i = 0; i < 2; i++)
#pragma unroll
        for (int j = 0; j < 4; j++)
#pragma unroll
            for (int q = 0; q < 4; q++) acc[i][j][q] = 0.f;

    const int nk = RKC >> 5;                      // 8
    load_stage(0);

    for (int kc = 0; kc < nk; kc++) {
        if (kc + 1 < nk) {
            load_stage(kc + 1);
            asm volatile("cp.async.wait_group 1;");
        } else {
            asm volatile("cp.async.wait_group 0;");
        }
        __syncthreads();

        const char* base = smem + (kc & 1) * FST;
#pragma unroll
        for (int kk = 0; kk < 2; kk++) {
            const int kb = kk * 32;
            uint32_t ah[2][4], al[2][4], bh[4][2];
#pragma unroll
            for (int i = 0; i < 2; i++) {
                int r0 = wm + i * 16 + gq;
                const char* pa = base + kb + 4 * tq;
                ah[i][0] = *(const uint32_t*)(pa + r0 * PITCH);
                ah[i][1] = *(const uint32_t*)(pa + (r0 + 8) * PITCH);
                ah[i][2] = *(const uint32_t*)(pa + r0 * PITCH + 16);
                ah[i][3] = *(const uint32_t*)(pa + (r0 + 8) * PITCH + 16);
                al[i][0] = *(const uint32_t*)(pa + FA_SZ + r0 * PITCH);
                al[i][1] = *(const uint32_t*)(pa + FA_SZ + (r0 + 8) * PITCH);
                al[i][2] = *(const uint32_t*)(pa + FA_SZ + r0 * PITCH + 16);
                al[i][3] = *(const uint32_t*)(pa + FA_SZ + (r0 + 8) * PITCH + 16);
            }
#pragma unroll
            for (int j = 0; j < 4; j++) {
                int rb = wn + j * 8 + gq;
                const char* pb = base + FB_OFF + kb + 4 * tq;
                bh[j][0] = *(const uint32_t*)(pb + rb * PITCH);
                bh[j][1] = *(const uint32_t*)(pb + rb * PITCH + 16);
            }
#pragma unroll
            for (int i = 0; i < 2; i++)
#pragma unroll
                for (int j = 0; j < 4; j++) {
                    mma16816h(acc[i][j], ah[i], bh[j]);
                    mma16816h(acc[i][j], al[i], bh[j]);
                }
        }
        __syncthreads();
    }

#pragma unroll
    for (int i = 0; i < 2; i++) {
        int r0 = wm + i * 16 + gq;
#pragma unroll
        for (int j = 0; j < 4; j++) {
            int col = bn + wn + j * 8 + 2 * tq;
            float* p0 = P + ((size_t)(ks * BB) + r0) * N + col;
            float* p1 = P + ((size_t)(ks * BB) + r0 + 8) * N + col;
            *(float2*)p0 = make_float2(acc[i][j][0], acc[i][j][1]);
            *(float2*)p1 = make_float2(acc[i][j][2], acc[i][j][3]);
        }
    }
}

// ---------------- encoder LSTM pointwise step ----------------
__global__ void k_enc_gate(int t)
{
    int gid = blockIdx.x * blockDim.x + threadIdx.x;
    int b = gid >> 10, u = gid & 1023;
    const float* xe = g_Xe + (size_t)(b * SS + t) * G4;
    float z[4];
#pragma unroll
    for (int gI = 0; gI < 4; gI++) {
        int col = gI * UU + u;
        float v = xe[col];
#pragma unroll
        for (int ks = 0; ks < RS; ks++) v += g_p[((size_t)ks * BB + b) * G4 + col];
        z[gI] = v;
    }
    float cprev = g_c[gid];
    float cn = sigf(z[1]) * cprev + sigf(z[0]) * tanhf(z[2]);
    float hn = sigf(z[3]) * tanhf(cn);
    g_c[gid] = cn;
    __half hh, hl; split1h(hn, hh, hl);
    g_hHi[gid] = hh; g_hLo[gid] = hl;
    g_o[(size_t)(b * SS + t) * UU + u] = hn;
}

// ---------------- fused decoder step: attention (blocks 0..63) + gate (64..319) ----
__global__ void __launch_bounds__(256)
k_dec_fused(int t, const float* __restrict__ ba)
{
    __shared__ float qs[UU];
    __shared__ float sc[SS];
    __shared__ float sinv;

    int tid = threadIdx.x;

    if (blockIdx.x < BB) {
        // ---------- attention for batch b (ctx -> hc fp16 directly) ----------
        int b = blockIdx.x;
        for (int u = tid; u < UU; u += 256) {
            float v = ba[u];
#pragma unroll
            for (int ks = 0; ks < RS; ks++) v += g_p[((size_t)ks * BB + b) * NC + u];
            qs[u] = v;
        }
        __syncthreads();

        int w = tid >> 5, lane = tid & 31;
        const float* ob = g_o + (size_t)b * SS * UU;
        for (int s = w; s < SS; s += 8) {
            const float* os = ob + (size_t)s * UU;
            float acc = 0.f;
            for (int u = lane; u < UU; u += 32) acc = fmaf(qs[u], os[u], acc);
#pragma unroll
            for (int off = 16; off; off >>= 1) acc += __shfl_xor_sync(0xffffffffu, acc, off);
            if (lane == 0) sc[s] = acc;
        }
        __syncthreads();

        if (tid == 0) {
            float mx = sc[0];
#pragma unroll
            for (int s = 1; s < SS; s++) mx = fmaxf(mx, sc[s]);
            float sum = 0.f;
            for (int s = 0; s < SS; s++) { float e = expf(sc[s] - mx); sc[s] = e; sum += e; }
            sinv = 1.f / sum;
        }
        __syncthreads();
        float inv = sinv;

        size_t rowb = (size_t)(b * TT + t) * U2;
        for (int u = tid; u < UU; u += 256) {
            float acc = 0.f;
#pragma unroll 8
            for (int s = 0; s < SS; s++) acc = fmaf(sc[s] * inv, ob[(size_t)s * UU + u], acc);
            g_hcH[rowb + u] = __float2half(acc);
        }
    } else {
        // ---------- LSTM gate (h -> hc fp16 + h hi/lo) ----------
        int gid = (blockIdx.x - BB) * 256 + tid;     // 0 .. B*U-1
        int b = gid >> 10, u = gid & 1023;
        const float* xd = g_Xd + (size_t)(b * TT + t) * G4;
        float z[4];
#pragma unroll
        for (int gI = 0; gI < 4; gI++) {
            int col = UU + gI * UU + u;              // z block sits after q block
#pragma unroll
            for (int ks = 0; ks < RS; ks++)
                z[gI] = (ks == 0 ? xd[gI * UU + u] : z[gI]) + g_p[((size_t)ks * BB + b) * NC + col];
        }
        float cprev = g_c[gid];
        float cn = sigf(z[1]) * cprev + sigf(z[0]) * tanhf(z[2]);
        float hn = sigf(z[3]) * tanhf(cn);
        g_c[gid] = cn;
        __half hh, hl; split1h(hn, hh, hl);
        g_hHi[gid] = hh; g_hLo[gid] = hl;
        g_hcH[(size_t)(b * TT + t) * U2 + UU + u] = __float2half(hn);
    }
}

// ---------------- launch ----------------
extern "C" void kernel_launch(void* const* d_in, const int* in_sizes, int n_in,
                              void* d_out, int out_size)
{
    const int*   x       = (const int*)d_in[0];
    const int*   y       = (const int*)d_in[1];
    const float* enc_emb = (const float*)d_in[2];
    const float* dec_emb = (const float*)d_in[3];
    const float* W_ih_e  = (const float*)d_in[4];
    const float* W_hh_e  = (const float*)d_in[5];
    const float* b_ih_e  = (const float*)d_in[6];
    const float* b_hh_e  = (const float*)d_in[7];
    const float* Wa      = (const float*)d_in[8];
    const float* ba      = (const float*)d_in[9];
    const float* W_ih_d  = (const float*)d_in[10];
    const float* W_hh_d  = (const float*)d_in[11];
    const float* b_ih_d  = (const float*)d_in[12];
    const float* b_hh_d  = (const float*)d_in[13];
    const float* Wd      = (const float*)d_in[14];
    const float* bd      = (const float*)d_in[15];
    float* out = (float*)d_out;

    float *pXe, *pXd, *pP;
    __half *pXeH, *pXdH, *pWeH, *pWidH, *pWdH, *pHcH, *pWhheH, *pWcatH;
    cudaGetSymbolAddress((void**)&pXe, g_Xe);
    cudaGetSymbolAddress((void**)&pXd, g_Xd);
    cudaGetSymbolAddress((void**)&pP,  g_p);
    cudaGetSymbolAddress((void**)&pXeH, g_XembEH);
    cudaGetSymbolAddress((void**)&pXdH, g_XembDH);
    cudaGetSymbolAddress((void**)&pWeH, g_WeH);
    cudaGetSymbolAddress((void**)&pWidH, g_WidH);
    cudaGetSymbolAddress((void**)&pWdH, g_WdH);
    cudaGetSymbolAddress((void**)&pHcH, g_hcH);
    cudaGetSymbolAddress((void**)&pWhheH, g_WhheH);
    cudaGetSymbolAddress((void**)&pWcatH, g_WcatH);

    // embeddings + init + weight converts (fp32 -> fp16)
    k_gather_enc<<<BB * SS * (EE / 4) / 256, 256>>>(x, enc_emb);
    k_gather_dec<<<BB * TT * (EE / 4) / 256, 256>>>(y, dec_emb);
    k_init_state<<<BB * UU / 256, 256>>>();
    {
        int n4 = G4 * EE / 4;
        k_cvt_half<<<(n4 + 255) / 256, 256>>>((const float4*)W_ih_e, (__half2*)pWeH, n4);
        k_cvt_half<<<(n4 + 255) / 256, 256>>>((const float4*)W_ih_d, (__half2*)pWidH, n4);
    }
    {
        int n4e = G4 * UU / 4;
        k_cvt_half<<<(n4e + 255) / 256, 256>>>((const float4*)W_hh_e, (__half2*)pWhheH, n4e);
        int n4a = UU * UU / 4;
        k_cvt_half<<<(n4a + 255) / 256, 256>>>((const float4*)Wa, (__half2*)pWcatH, n4a);
        int n4d = G4 * UU / 4;
        k_cvt_half<<<(n4d + 255) / 256, 256>>>((const float4*)W_hh_d,
            (__half2*)(pWcatH + (size_t)UU * UU), n4d);
    }
    {
        int n4 = (int)((size_t)VD_ * U2 / 4);
        k_cvt_half<<<(n4 + 255) / 256, 256>>>((const float4*)Wd, (__half2*)pWdH, n4);
    }

    // time-batched input projections (fp16 single-pass)
    k_hf16<0><<<dim3(G4 / 128, (BB * SS) / 128), 256>>>(
        pXeH, pWeH, b_ih_e, b_hh_e, pXe, BB * SS, G4, EE);
    k_hf16<0><<<dim3(G4 / 128, (BB * TT) / 128), 256>>>(
        pXdH, pWidH, b_ih_d, b_hh_d, pXd, BB * TT, G4, EE);

    // encoder recurrence (fp16 2-pass GEMM + gate)
    for (int t = 0; t < SS; t++) {
        k_rec_f16<<<dim3(G4 / 128, RS), 256>>>(pWhheH, pP, G4);
        k_enc_gate<<<BB * UU / 256, 256>>>(t);
    }

    // decoder recurrence: one combined GEMM (q ‖ z) + one fused attn/gate kernel per step
    for (int t = 0; t < TT; t++) {
        k_rec_f16<<<dim3(NC / 128, RS), 256>>>(pWcatH, pP, NC);
        k_dec_fused<<<BB + BB * UU / 256, 256>>>(t, ba);
    }

    // batched logits: single-pass fp16 (A = Wd rows, B = hc rows)
    k_hf16<1><<<dim3((BB * TT) / 128, VD_ / 128), 256>>>(
        pWdH, pHcH, bd, nullptr, out, VD_, BB * TT, U2);
}

// round 17
// speedup vs baseline: 1.7799x; 1.0055x over previous
#include <cuda_runtime.h>
#include <cuda_fp16.h>
#include <math.h>
#include <stdint.h>

// ---------------- problem constants ----------------
#define BB   64
#define SS   64
#define TT   32
#define EE   512
#define UU   1024
#define G4   (4*UU)      // 4096
#define U2   (2*UU)      // 2048
#define NC   (UU+G4)     // 5120 (Wa ‖ W_hh_d rows)
#define VD_  32000
#define RS   4           // recurrence K-split
#define RKC  (UU/RS)     // 256

// ---------------- device scratch (allocation-free contract) ----------------
__device__ __half g_XembEH[(size_t)BB*SS*EE];
__device__ __half g_XembDH[(size_t)BB*TT*EE];
__device__ __half g_WeH [(size_t)G4*EE];
__device__ __half g_WidH[(size_t)G4*EE];
__device__ __half g_WdH [(size_t)VD_*U2];
__device__ __half g_hcH [(size_t)BB*TT*U2];       // fp16 [b*T+t][ctx|h]

// recurrence fp16 weights + fp16 hi/lo h state
__device__ __half g_WhheH[(size_t)G4*UU];
__device__ __half g_WcatH[(size_t)NC*UU];         // rows 0..1023 = Wa, 1024.. = W_hh_d
__device__ __half g_hHi[BB*UU];
__device__ __half g_hLo[BB*UU];

__device__ float g_Xe[(size_t)BB*SS*G4];          // x@W_ih_e^T + biases
__device__ float g_Xd[(size_t)BB*TT*G4];
__device__ float g_o [(size_t)BB*SS*UU];          // encoder outputs (fp32)
__device__ float g_c [BB*UU];
__device__ float g_p [(size_t)RS*BB*NC];          // K-split partials

// ---------------- helpers ----------------
__device__ __forceinline__ float sigf(float x) { return 1.f / (1.f + expf(-x)); }

__device__ __forceinline__ void cp16(void* dst, const void* src) {
    uint32_t a;
    asm("{ .reg .u64 t; cvta.to.shared.u64 t, %1; cvt.u32.u64 %0, t; }"
        : "=r"(a) : "l"(dst));
    asm volatile("cp.async.cg.shared.global [%0], [%1], 16;" :: "r"(a), "l"(src));
}

__device__ __forceinline__ void mma16816h(float* c, const uint32_t* a, const uint32_t* b) {
    asm volatile(
        "mma.sync.aligned.m16n8k16.row.col.f32.f16.f16.f32 "
        "{%0,%1,%2,%3}, {%4,%5,%6,%7}, {%8,%9}, {%0,%1,%2,%3};"
        : "+f"(c[0]), "+f"(c[1]), "+f"(c[2]), "+f"(c[3])
        : "r"(a[0]), "r"(a[1]), "r"(a[2]), "r"(a[3]), "r"(b[0]), "r"(b[1]));
}

__device__ __forceinline__ void split1h(float x, __half& h, __half& l) {
    h = __float2half(x);
    l = __float2half(x - __half2float(h));
}

// ---------------- fp32 -> fp16 convert ----------------
__global__ void k_cvt_half(const float4* __restrict__ src,
                           __half2* __restrict__ dst, int n4)
{
    int gid = blockIdx.x * blockDim.x + threadIdx.x;
    if (gid >= n4) return;
    float4 v = src[gid];
    dst[gid * 2]     = __floats2half2_rn(v.x, v.y);
    dst[gid * 2 + 1] = __floats2half2_rn(v.z, v.w);
}

// ---------------- embedding gathers (write fp16) ----------------
__global__ void k_gather_enc(const int* __restrict__ x, const float* __restrict__ emb) {
    int gid = blockIdx.x * blockDim.x + threadIdx.x;      // BB*SS*(EE/4)
    const int E4 = EE / 4;
    int r = gid / E4, c = gid % E4;
    float4 v = ((const float4*)emb)[(size_t)x[r] * E4 + c];
    ((__half2*)g_XembEH)[gid * 2]     = __floats2half2_rn(v.x, v.y);
    ((__half2*)g_XembEH)[gid * 2 + 1] = __floats2half2_rn(v.z, v.w);
}

__global__ void k_gather_dec(const int* __restrict__ y, const float* __restrict__ emb) {
    int gid = blockIdx.x * blockDim.x + threadIdx.x;      // BB*TT*(EE/4)
    const int E4 = EE / 4;
    int r = gid / E4, c = gid % E4;
    int b = r / TT, t = r % TT;
    int id = y[b * (TT + 1) + t];
    float4 v = ((const float4*)emb)[(size_t)id * E4 + c];
    ((__half2*)g_XembDH)[gid * 2]     = __floats2half2_rn(v.x, v.y);
    ((__half2*)g_XembDH)[gid * 2 + 1] = __floats2half2_rn(v.z, v.w);
}

__global__ void k_init_state() {
    int gid = blockIdx.x * blockDim.x + threadIdx.x;
    if (gid < BB * UU) {
        g_c[gid] = 0.f;
        g_hHi[gid] = __float2half(0.f);
        g_hLo[gid] = __float2half(0.f);
    }
}

// ---------------- fp16 single-pass GEMM (projections + logits), 128x128 tile ------
// MODE 0: C[m*N+n] = A[m].B[n] + bias1[n] + bias2[n]   (A=Xemb, B=W_ih)
// MODE 1: C[((n>>5)*VD + m)*32 + (n&31)] = A[m].B[n] + bias1[m]  (A=Wd, B=hc)
#define PITCH   80
#define HARR    (128 * PITCH)           // 10240
#define HSTG    (2 * HARR)              // 20480 per stage

template <int MODE>
__global__ void __launch_bounds__(256)
k_hf16(const __half* __restrict__ A, const __half* __restrict__ B,
       const float* __restrict__ bias1, const float* __restrict__ bias2,
       float* __restrict__ C, int M, int N, int K)
{
    __shared__ __align__(16) char smem[2 * HSTG];   // 40 KB

    const int tid = threadIdx.x;
    const int wid = tid >> 5, lane = tid & 31;
    const int gq = lane >> 2, tq = lane & 3;
    const int wm = (wid >> 2) * 64;
    const int wn = (wid & 3) * 32;
    const int bm = blockIdx.y * 128, bn = blockIdx.x * 128;
    const int nk = K >> 5;

    auto load_stage = [&](int kc) {
        char* base = smem + (kc & 1) * HSTG;
        int k0 = kc << 5;
#pragma unroll
        for (int i = 0; i < 4; i++) {
            int e = tid + i * 256;
            int arr = e >> 9;
            int r = (e >> 2) & 127;
            int seg = e & 3;
            const __half* src = (arr ? B + (size_t)(bn + r) * K
                                     : A + (size_t)(bm + r) * K) + k0 + seg * 8;
            cp16(base + arr * HARR + r * PITCH + seg * 16, src);
        }
        asm volatile("cp.async.commit_group;");
    };

    float acc[4][4][4];
#pragma unroll
    for (int i = 0; i < 4; i++)
#pragma unroll
        for (int j = 0; j < 4; j++)
#pragma unroll
            for (int q = 0; q < 4; q++) acc[i][j][q] = 0.f;

    load_stage(0);

    for (int kc = 0; kc < nk; kc++) {
        if (kc + 1 < nk) {
            load_stage(kc + 1);
            asm volatile("cp.async.wait_group 1;");
        } else {
            asm volatile("cp.async.wait_group 0;");
        }
        __syncthreads();

        const char* base = smem + (kc & 1) * HSTG;
#pragma unroll
        for (int kk = 0; kk < 2; kk++) {
            const int kb = kk * 32;
            uint32_t ah[4][4], bh[4][2];
#pragma unroll
            for (int i = 0; i < 4; i++) {
                int r0 = wm + i * 16 + gq;
                const char* pa = base + kb + 4 * tq;
                ah[i][0] = *(const uint32_t*)(pa + r0 * PITCH);
                ah[i][1] = *(const uint32_t*)(pa + (r0 + 8) * PITCH);
                ah[i][2] = *(const uint32_t*)(pa + r0 * PITCH + 16);
                ah[i][3] = *(const uint32_t*)(pa + (r0 + 8) * PITCH + 16);
            }
#pragma unroll
            for (int j = 0; j < 4; j++) {
                int rb = wn + j * 8 + gq;
                const char* pb = base + HARR + kb + 4 * tq;
                bh[j][0] = *(const uint32_t*)(pb + rb * PITCH);
                bh[j][1] = *(const uint32_t*)(pb + rb * PITCH + 16);
            }
#pragma unroll
            for (int i = 0; i < 4; i++)
#pragma unroll
                for (int j = 0; j < 4; j++)
                    mma16816h(acc[i][j], ah[i], bh[j]);
        }
        __syncthreads();
    }

#pragma unroll
    for (int i = 0; i < 4; i++) {
        int r0 = bm + wm + i * 16 + gq;
        if (MODE == 0) {
#pragma unroll
            for (int j = 0; j < 4; j++) {
                int col = bn + wn + j * 8 + 2 * tq;
                float b0 = bias1[col] + bias2[col];
                float b1 = bias1[col + 1] + bias2[col + 1];
                float2 v0 = make_float2(acc[i][j][0] + b0, acc[i][j][1] + b1);
                float2 v1 = make_float2(acc[i][j][2] + b0, acc[i][j][3] + b1);
                *(float2*)(C + (size_t)r0 * N + col) = v0;
                *(float2*)(C + (size_t)(r0 + 8) * N + col) = v1;
            }
        } else {
            float bv0 = bias1[r0];
            float bv1 = bias1[r0 + 8];
#pragma unroll
            for (int j = 0; j < 4; j++) {
                int col = bn + wn + j * 8 + 2 * tq;
                int b = col >> 5, t = col & 31;
                float* p0 = C + ((size_t)b * VD_ + r0) * 32 + t;
                float* p1 = C + ((size_t)b * VD_ + r0 + 8) * 32 + t;
                *(float2*)p0 = make_float2(acc[i][j][0] + bv0, acc[i][j][1] + bv0);
                *(float2*)p1 = make_float2(acc[i][j][2] + bv1, acc[i][j][3] + bv1);
            }
        }
    }
}

// ---------------- fp16 2-pass recurrence GEMM ----------------
// P[ks][64][N] = (hHi+hLo)[64,1024] @ W[N,1024]^T (K chunk ks), fp32 accum.
#define FA_SZ  (64 * PITCH)             // 5120
#define FB_OFF (2 * FA_SZ)              // 10240
#define FST    (2 * FA_SZ + 128 * PITCH)   // 20480 per stage

__global__ void __launch_bounds__(256)
k_rec_f16(const __half* __restrict__ W, float* __restrict__ P, int N)
{
    __shared__ __align__(16) char smem[2 * FST];    // 40 KB

    const int tid = threadIdx.x;
    const int wid = tid >> 5, lane = tid & 31;
    const int gq = lane >> 2, tq = lane & 3;
    const int wm = (wid >> 2) * 32;               // 0,32
    const int wn = (wid & 3) * 32;                // 0..96
    const int bn = blockIdx.x * 128;
    const int ks = blockIdx.y;
    const int kbase = ks * RKC;

    auto load_stage = [&](int kc) {
        char* base = smem + (kc & 1) * FST;
        int k0 = kbase + (kc << 5);
#pragma unroll
        for (int i = 0; i < 4; i++) {
            int e = tid + i * 256;                // 0..1023
            const __half* src;
            char* dst;
            if (e < 512) {                        // A hi/lo: 64 rows x 4 segs x 2
                int arr = e >> 8;
                int r = (e >> 2) & 63, seg = e & 3;
                src = (arr ? g_hLo : g_hHi) + (size_t)r * UU + k0 + seg * 8;
                dst = base + arr * FA_SZ + r * PITCH + seg * 16;
            } else {                              // B: 128 rows x 4 segs
                int e2 = e - 512;
                int r = (e2 >> 2) & 127, seg = e2 & 3;
                src = W + (size_t)(bn + r) * UU + k0 + seg * 8;
                dst = base + FB_OFF + r * PITCH + seg * 16;
            }
            cp16(dst, src);
        }
        asm volatile("cp.async.commit_group;");
    };

    float acc[2][4][4];
#pragma unroll
    for (int i = 0; i < 2; i++)
#pragma unroll
        for (int j = 0; j < 4; j++)
#pragma unroll
            for (int q = 0; q < 4; q++) acc[i][j][q] = 0.f;

    const int nk = RKC >> 5;                      // 8
    load_stage(0);

    for (int kc = 0; kc < nk; kc++) {
        if (kc + 1 < nk) {
            load_stage(kc + 1);
            asm volatile("cp.async.wait_group 1;");
        } else {
            asm volatile("cp.async.wait_group 0;");
        }
        __syncthreads();

        const char* base = smem + (kc & 1) * FST;
#pragma unroll
        for (int kk = 0; kk < 2; kk++) {
            const int kb = kk * 32;
            uint32_t ah[2][4], al[2][4], bh[4][2];
#pragma unroll
            for (int i = 0; i < 2; i++) {
                int r0 = wm + i * 16 + gq;
                const char* pa = base + kb + 4 * tq;
                ah[i][0] = *(const uint32_t*)(pa + r0 * PITCH);
                ah[i][1] = *(const uint32_t*)(pa + (r0 + 8) * PITCH);
                ah[i][2] = *(const uint32_t*)(pa + r0 * PITCH + 16);
                ah[i][3] = *(const uint32_t*)(pa + (r0 + 8) * PITCH + 16);
                al[i][0] = *(const uint32_t*)(pa + FA_SZ + r0 * PITCH);
                al[i][1] = *(const uint32_t*)(pa + FA_SZ + (r0 + 8) * PITCH);
                al[i][2] = *(const uint32_t*)(pa + FA_SZ + r0 * PITCH + 16);
                al[i][3] = *(const uint32_t*)(pa + FA_SZ + (r0 + 8) * PITCH + 16);
            }
#pragma unroll
            for (int j = 0; j < 4; j++) {
                int rb = wn + j * 8 + gq;
                const char* pb = base + FB_OFF + kb + 4 * tq;
                bh[j][0] = *(const uint32_t*)(pb + rb * PITCH);
                bh[j][1] = *(const uint32_t*)(pb + rb * PITCH + 16);
            }
#pragma unroll
            for (int i = 0; i < 2; i++)
#pragma unroll
                for (int j = 0; j < 4; j++) {
                    mma16816h(acc[i][j], ah[i], bh[j]);
                    mma16816h(acc[i][j], al[i], bh[j]);
                }
        }
        __syncthreads();
    }

#pragma unroll
    for (int i = 0; i < 2; i++) {
        int r0 = wm + i * 16 + gq;
#pragma unroll
        for (int j = 0; j < 4; j++) {
            int col = bn + wn + j * 8 + 2 * tq;
            float* p0 = P + ((size_t)(ks * BB) + r0) * N + col;
            float* p1 = P + ((size_t)(ks * BB) + r0 + 8) * N + col;
            *(float2*)p0 = make_float2(acc[i][j][0], acc[i][j][1]);
            *(float2*)p1 = make_float2(acc[i][j][2], acc[i][j][3]);
        }
    }
}

// ---------------- encoder LSTM pointwise step ----------------
__global__ void k_enc_gate(int t)
{
    int gid = blockIdx.x * blockDim.x + threadIdx.x;
    int b = gid >> 10, u = gid & 1023;
    const float* xe = g_Xe + (size_t)(b * SS + t) * G4;
    float z[4];
#pragma unroll
    for (int gI = 0; gI < 4; gI++) {
        int col = gI * UU + u;
        float v = xe[col];
#pragma unroll
        for (int ks = 0; ks < RS; ks++) v += g_p[((size_t)ks * BB + b) * G4 + col];
        z[gI] = v;
    }
    float cprev = g_c[gid];
    float cn = sigf(z[1]) * cprev + sigf(z[0]) * tanhf(z[2]);
    float hn = sigf(z[3]) * tanhf(cn);
    g_c[gid] = cn;
    __half hh, hl; split1h(hn, hh, hl);
    g_hHi[gid] = hh; g_hLo[gid] = hl;
    g_o[(size_t)(b * SS + t) * UU + u] = hn;
}

// ---------------- fused decoder step: attention (blocks 0..63) + gate (64..319) ----
__global__ void __launch_bounds__(256)
k_dec_fused(int t, const float* __restrict__ ba)
{
    __shared__ float qs[UU];
    __shared__ float sc[SS];
    __shared__ float sinv;

    int tid = threadIdx.x;

    if (blockIdx.x < BB) {
        // ---------- attention for batch b (ctx -> hc fp16 directly) ----------
        int b = blockIdx.x;
        for (int u = tid; u < UU; u += 256) {
            float v = ba[u];
#pragma unroll
            for (int ks = 0; ks < RS; ks++) v += g_p[((size_t)ks * BB + b) * NC + u];
            qs[u] = v;
        }
        __syncthreads();

        int w = tid >> 5, lane = tid & 31;
        const float* ob = g_o + (size_t)b * SS * UU;
        for (int s = w; s < SS; s += 8) {
            const float* os = ob + (size_t)s * UU;
            float acc = 0.f;
            for (int u = lane; u < UU; u += 32) acc = fmaf(qs[u], os[u], acc);
#pragma unroll
            for (int off = 16; off; off >>= 1) acc += __shfl_xor_sync(0xffffffffu, acc, off);
            if (lane == 0) sc[s] = acc;
        }
        __syncthreads();

        if (tid == 0) {
            float mx = sc[0];
#pragma unroll
            for (int s = 1; s < SS; s++) mx = fmaxf(mx, sc[s]);
            float sum = 0.f;
            for (int s = 0; s < SS; s++) { float e = expf(sc[s] - mx); sc[s] = e; sum += e; }
            sinv = 1.f / sum;
        }
        __syncthreads();
        float inv = sinv;

        size_t rowb = (size_t)(b * TT + t) * U2;
        for (int u = tid; u < UU; u += 256) {
            float acc = 0.f;
#pragma unroll 8
            for (int s = 0; s < SS; s++) acc = fmaf(sc[s] * inv, ob[(size_t)s * UU + u], acc);
            g_hcH[rowb + u] = __float2half(acc);
        }
    } else {
        // ---------- LSTM gate (h -> hc fp16 + h hi/lo) ----------
        int gid = (blockIdx.x - BB) * 256 + tid;     // 0 .. B*U-1
        int b = gid >> 10, u = gid & 1023;
        const float* xd = g_Xd + (size_t)(b * TT + t) * G4;
        float z[4];
#pragma unroll
        for (int gI = 0; gI < 4; gI++) {
            int col = UU + gI * UU + u;              // z block sits after q block
#pragma unroll
            for (int ks = 0; ks < RS; ks++)
                z[gI] = (ks == 0 ? xd[gI * UU + u] : z[gI]) + g_p[((size_t)ks * BB + b) * NC + col];
        }
        float cprev = g_c[gid];
        float cn = sigf(z[1]) * cprev + sigf(z[0]) * tanhf(z[2]);
        float hn = sigf(z[3]) * tanhf(cn);
        g_c[gid] = cn;
        __half hh, hl; split1h(hn, hh, hl);
        g_hHi[gid] = hh; g_hLo[gid] = hl;
        g_hcH[(size_t)(b * TT + t) * U2 + UU + u] = __float2half(hn);
    }
}

// ---------------- launch ----------------
extern "C" void kernel_launch(void* const* d_in, const int* in_sizes, int n_in,
                              void* d_out, int out_size)
{
    const int*   x       = (const int*)d_in[0];
    const int*   y       = (const int*)d_in[1];
    const float* enc_emb = (const float*)d_in[2];
    const float* dec_emb = (const float*)d_in[3];
    const float* W_ih_e  = (const float*)d_in[4];
    const float* W_hh_e  = (const float*)d_in[5];
    const float* b_ih_e  = (const float*)d_in[6];
    const float* b_hh_e  = (const float*)d_in[7];
    const float* Wa      = (const float*)d_in[8];
    const float* ba      = (const float*)d_in[9];
    const float* W_ih_d  = (const float*)d_in[10];
    const float* W_hh_d  = (const float*)d_in[11];
    const float* b_ih_d  = (const float*)d_in[12];
    const float* b_hh_d  = (const float*)d_in[13];
    const float* Wd      = (const float*)d_in[14];
    const float* bd      = (const float*)d_in[15];
    float* out = (float*)d_out;

    float *pXe, *pXd, *pP;
    __half *pXeH, *pXdH, *pWeH, *pWidH, *pWdH, *pHcH, *pWhheH, *pWcatH;
    cudaGetSymbolAddress((void**)&pXe, g_Xe);
    cudaGetSymbolAddress((void**)&pXd, g_Xd);
    cudaGetSymbolAddress((void**)&pP,  g_p);
    cudaGetSymbolAddress((void**)&pXeH, g_XembEH);
    cudaGetSymbolAddress((void**)&pXdH, g_XembDH);
    cudaGetSymbolAddress((void**)&pWeH, g_WeH);
    cudaGetSymbolAddress((void**)&pWidH, g_WidH);
    cudaGetSymbolAddress((void**)&pWdH, g_WdH);
    cudaGetSymbolAddress((void**)&pHcH, g_hcH);
    cudaGetSymbolAddress((void**)&pWhheH, g_WhheH);
    cudaGetSymbolAddress((void**)&pWcatH, g_WcatH);

    // side stream + events (created once; resource-only statics, work is identical
    // on every call so determinism holds)
    static cudaStream_t s_side = nullptr;
    static cudaEvent_t evFork = nullptr, evDec = nullptr, evWd = nullptr;
    if (!s_side) {
        cudaStreamCreateWithFlags(&s_side, cudaStreamNonBlocking);
        cudaEventCreateWithFlags(&evFork, cudaEventDisableTiming);
        cudaEventCreateWithFlags(&evDec,  cudaEventDisableTiming);
        cudaEventCreateWithFlags(&evWd,   cudaEventDisableTiming);
    }

    // ---- fork: side stream handles all decoder-side + logits-side prep ----
    cudaEventRecord(evFork, 0);
    cudaStreamWaitEvent(s_side, evFork, 0);
    {
        k_gather_dec<<<BB * TT * (EE / 4) / 256, 256, 0, s_side>>>(y, dec_emb);
        int n4 = G4 * EE / 4;
        k_cvt_half<<<(n4 + 255) / 256, 256, 0, s_side>>>(
            (const float4*)W_ih_d, (__half2*)pWidH, n4);
        int n4a = UU * UU / 4;
        k_cvt_half<<<(n4a + 255) / 256, 256, 0, s_side>>>(
            (const float4*)Wa, (__half2*)pWcatH, n4a);
        int n4d = G4 * UU / 4;
        k_cvt_half<<<(n4d + 255) / 256, 256, 0, s_side>>>(
            (const float4*)W_hh_d, (__half2*)(pWcatH + (size_t)UU * UU), n4d);
        // decoder input projection
        k_hf16<0><<<dim3(G4 / 128, (BB * TT) / 128), 256, 0, s_side>>>(
            pXdH, pWidH, b_ih_d, b_hh_d, pXd, BB * TT, G4, EE);
        cudaEventRecord(evDec, s_side);
        // Wd convert (only needed by final logits GEMM)
        int n4w = (int)((size_t)VD_ * U2 / 4);
        k_cvt_half<<<(n4w + 255) / 256, 256, 0, s_side>>>(
            (const float4*)Wd, (__half2*)pWdH, n4w);
        cudaEventRecord(evWd, s_side);
    }

    // ---- main chain: encoder-side prep ----
    k_gather_enc<<<BB * SS * (EE / 4) / 256, 256>>>(x, enc_emb);
    k_init_state<<<BB * UU / 256, 256>>>();
    {
        int n4 = G4 * EE / 4;
        k_cvt_half<<<(n4 + 255) / 256, 256>>>((const float4*)W_ih_e, (__half2*)pWeH, n4);
        int n4e = G4 * UU / 4;
        k_cvt_half<<<(n4e + 255) / 256, 256>>>((const float4*)W_hh_e, (__half2*)pWhheH, n4e);
    }
    k_hf16<0><<<dim3(G4 / 128, (BB * SS) / 128), 256>>>(
        pXeH, pWeH, b_ih_e, b_hh_e, pXe, BB * SS, G4, EE);

    // encoder recurrence (fp16 2-pass GEMM + gate)
    for (int t = 0; t < SS; t++) {
        k_rec_f16<<<dim3(G4 / 128, RS), 256>>>(pWhheH, pP, G4);
        k_enc_gate<<<BB * UU / 256, 256>>>(t);
    }

    // join decoder-side prep before decoder loop
    cudaStreamWaitEvent(0, evDec, 0);

    // decoder recurrence: one combined GEMM (q ‖ z) + one fused attn/gate per step
    for (int t = 0; t < TT; t++) {
        k_rec_f16<<<dim3(NC / 128, RS), 256>>>(pWcatH, pP, NC);
        k_dec_fused<<<BB + BB * UU / 256, 256>>>(t, ba);
    }

    // join Wd convert before logits
    cudaStreamWaitEvent(0, evWd, 0);

    // batched logits: single-pass fp16 (A = Wd rows, B = hc rows)
    k_hf16<1><<<dim3((BB * TT) / 128, VD_ / 128), 256>>>(
        pWdH, pHcH, bd, nullptr, out, VD_, BB * TT, U2);
}